// round 1
// baseline (speedup 1.0000x reference)
#include <cuda_runtime.h>
#include <cuda_bf16.h>
#include <math.h>

// Problem constants
#define V   32000
#define D   256
#define UH  512
#define BB  16
#define TT  128
#define NS  126          // effective recurrent steps / output timesteps
#define G4  2048         // 4*U
#define OROWS (BB*NS)    // 2016
#define OC  1024         // 2*U

typedef unsigned long long ull;

// ---------------- device scratch (no allocations allowed) ----------------
__device__ float g_emb[BB*TT*D];            // [b][t][d]
__device__ float g_X[2][NS*BB*G4];          // per dir: [t][b][4U]  (x@W0 + b0)
__device__ float g_h0[2][2][BB*UH];         // [dir][parity][b][u]
__device__ float g_h1[2][2][BB*UH];
__device__ float g_c0[2][BB*UH];
__device__ float g_c1[2][BB*UH];
__device__ float g_o[(size_t)OROWS*OC];     // concat(f, b_rev) rows

// ---------------- f32x2 packed FMA helpers (FFMA2, sm_100+) ----------------
__device__ __forceinline__ ull pack2(float lo, float hi){
    ull r;
    asm("mov.b64 %0, {%1,%2};" : "=l"(r)
        : "r"(__float_as_uint(lo)), "r"(__float_as_uint(hi)));
    return r;
}
__device__ __forceinline__ void unpack2(ull v, float& lo, float& hi){
    unsigned a, b;
    asm("mov.b64 {%0,%1}, %2;" : "=r"(a), "=r"(b) : "l"(v));
    lo = __uint_as_float(a); hi = __uint_as_float(b);
}
__device__ __forceinline__ ull ffma2(ull a, ull b, ull c){
    ull r;
    asm("fma.rn.f32x2 %0, %1, %2, %3;" : "=l"(r) : "l"(a), "l"(b), "l"(c));
    return r;
}
__device__ __forceinline__ float sigf(float x){ return 1.f/(1.f + __expf(-x)); }

// ---------------- init: zero recurrent state (must run every replay) ----------------
__global__ void k_init(){
    int i = blockIdx.x*blockDim.x + threadIdx.x;
    if (i >= BB*UH) return;
    #pragma unroll
    for (int d2=0; d2<2; d2++){
        g_h0[d2][0][i]=0.f; g_h0[d2][1][i]=0.f;
        g_h1[d2][0][i]=0.f; g_h1[d2][1][i]=0.f;
        g_c0[d2][i]=0.f;    g_c1[d2][i]=0.f;
    }
}

// ---------------- embedding gather ----------------
__global__ void k_embed(const int* __restrict__ seqs, const float* __restrict__ embed){
    int i = blockIdx.x*blockDim.x + threadIdx.x;      // over BB*TT*(D/4)
    if (i >= BB*TT*(D/4)) return;
    int bt = i / (D/4);
    int d4 = i % (D/4);
    int tok = seqs[bt];
    float4 v = *(const float4*)&embed[(size_t)tok*D + d4*4];
    *(float4*)&g_emb[(size_t)bt*D + d4*4] = v;
}

// ---------------- X precompute: g_X[dir][(t*16+b)*2048+j] = emb@W0 + b0 ----------------
// Tiled fp32 GEMM, BM=128, BN=256, BK=16, 256 threads, 8x16 microtile via FFMA2.
__global__ __launch_bounds__(256) void k_xprep(const float* __restrict__ fW0,
                                               const float* __restrict__ fb0,
                                               const float* __restrict__ bW0,
                                               const float* __restrict__ bb0){
    const int dir = blockIdx.z;
    const float* W    = dir ? bW0 : fW0;
    const float* bias = dir ? bb0 : fb0;
    float* out = g_X[dir];
    const int m0 = blockIdx.y*128, n0 = blockIdx.x*256;
    __shared__ float As[16][128];
    __shared__ float Bs[16][256];
    const int tid = threadIdx.x;
    const int tx = tid & 15, ty = tid >> 4;

    ull acc[8][8];
    #pragma unroll
    for (int i=0;i<8;i++)
        #pragma unroll
        for (int q=0;q<8;q++) acc[i][q] = 0ull;

    for (int kt=0; kt<16; kt++){         // K = 256
        #pragma unroll
        for (int i=0;i<2;i++){
            int lin = tid + i*256;
            int row = lin>>2, c4 = lin&3;
            int r = m0 + row;
            float4 v = make_float4(0.f,0.f,0.f,0.f);
            if (r < OROWS){
                int t = r>>4, b = r&15;
                int txi = dir ? (127 - t) : t;
                v = *(const float4*)&g_emb[((b<<7)+txi)*D + kt*16 + c4*4];
            }
            As[c4*4+0][row]=v.x; As[c4*4+1][row]=v.y;
            As[c4*4+2][row]=v.z; As[c4*4+3][row]=v.w;
        }
        #pragma unroll
        for (int i=0;i<4;i++){
            int lin = tid + i*256;
            int kr = lin>>6, c4 = lin&63;
            *(float4*)&Bs[kr][c4*4] =
                *(const float4*)&W[(size_t)(kt*16+kr)*G4 + n0 + c4*4];
        }
        __syncthreads();
        #pragma unroll
        for (int k=0;k<16;k++){
            float a0[8];
            *(float4*)&a0[0] = *(float4*)&As[k][ty*8];
            *(float4*)&a0[4] = *(float4*)&As[k][ty*8+4];
            ull av[8];
            #pragma unroll
            for (int i=0;i<8;i++) av[i] = pack2(a0[i], a0[i]);
            ull bv[8];
            #pragma unroll
            for (int q=0;q<4;q++){
                ulonglong2 p = *(const ulonglong2*)&Bs[k][tx*16 + q*4];
                bv[2*q] = p.x; bv[2*q+1] = p.y;
            }
            #pragma unroll
            for (int i=0;i<8;i++)
                #pragma unroll
                for (int q=0;q<8;q++)
                    acc[i][q] = ffma2(av[i], bv[q], acc[i][q]);
        }
        __syncthreads();
    }
    #pragma unroll
    for (int i=0;i<8;i++){
        int r = m0 + ty*8 + i;
        if (r >= OROWS) continue;
        float* crow = out + (size_t)r*G4 + n0 + tx*16;
        #pragma unroll
        for (int q=0;q<8;q++){
            float lo,hi; unpack2(acc[i][q], lo, hi);
            int col = n0 + tx*16 + 2*q;
            float2 st; st.x = lo + bias[col]; st.y = hi + bias[col+1];
            *(float2*)&crow[2*q] = st;
        }
    }
}

// ---------------- one recurrent step (layer0 @ s, layer1 @ s-1 pipelined) ----------------
// Grid: 128 blocks x 128 threads. cell = bx>>5 (dir = cell>>1, layer = cell&1),
// chunk = bx&31 -> 16 hidden units per block across all 4 gates and all 16 batches.
// Each thread: 64 j-columns split as (bh half of batch pairs) -> 4 f32x2 accumulators.
__global__ __launch_bounds__(128) void k_step(int s,
    const float* __restrict__ fU0, const float* __restrict__ fW1,
    const float* __restrict__ fU1, const float* __restrict__ fb1,
    const float* __restrict__ bU0, const float* __restrict__ bW1,
    const float* __restrict__ bU1, const float* __restrict__ bb1,
    const int*   __restrict__ seqs)
{
    extern __shared__ float sm[];
    float* ht0 = sm;                  // transposed h: [k][18] (16 used, pad to 18)
    float* ht1 = sm + 512*18;
    float* zs  = sm + 2*512*18;       // [16][64] gate pre-activations

    const int tid   = threadIdx.x;
    const int cell  = blockIdx.x >> 5;
    const int layer = cell & 1;
    const int dir   = cell >> 1;
    const int chunk = blockIdx.x & 31;
    const int u0    = chunk * 16;

    int t = layer ? (s-1) : s;
    if (layer==0 && t >= NS) return;
    if (layer==1 && t < 0)   return;
    const int pp = (t-1)&1, pc = t&1;

    // load h state(s) transposed into smem
    if (layer==0){
        const float* hp = g_h0[dir][pp];
        #pragma unroll 8
        for (int i=0;i<64;i++){
            int idx = i*128 + tid;
            ht0[(idx & 511)*18 + (idx>>9)] = hp[idx];
        }
    } else {
        const float* hx = g_h0[dir][pc];   // layer0 output at step t (prev kernel)
        const float* hp = g_h1[dir][pp];
        #pragma unroll 8
        for (int i=0;i<64;i++){
            int idx = i*128 + tid;
            int off = (idx & 511)*18 + (idx>>9);
            ht0[off] = hx[idx];
            ht1[off] = hp[idx];
        }
    }
    __syncthreads();

    const int jj    = tid & 63;
    const int bh    = tid >> 6;          // batch-half
    const int gate  = jj >> 4;
    const int j     = gate*512 + u0 + (jj & 15);
    const int pbase = bh*4;              // batch-pair base

    ull acc[4];
    if (layer==0){
        const float* X = g_X[dir] + (size_t)t*BB*G4;
        #pragma unroll
        for (int p=0;p<4;p++){
            int b = 2*(pbase+p);
            acc[p] = pack2(X[b*G4 + j], X[(b+1)*G4 + j]);
        }
        const float* W = dir ? bU0 : fU0;
        #pragma unroll 8
        for (int k=0;k<UH;k++){
            float w = W[k*G4 + j];
            ull ww = pack2(w,w);
            #pragma unroll
            for (int p=0;p<4;p++)
                acc[p] = ffma2(ww, *(const ull*)&ht0[k*18 + 2*(pbase+p)], acc[p]);
        }
    } else {
        float bias = (dir ? bb1 : fb1)[j];
        #pragma unroll
        for (int p=0;p<4;p++) acc[p] = pack2(bias, bias);
        const float* W1 = dir ? bW1 : fW1;
        const float* U1 = dir ? bU1 : fU1;
        #pragma unroll 8
        for (int k=0;k<UH;k++){
            float w = W1[k*G4 + j];
            ull ww = pack2(w,w);
            #pragma unroll
            for (int p=0;p<4;p++)
                acc[p] = ffma2(ww, *(const ull*)&ht0[k*18 + 2*(pbase+p)], acc[p]);
        }
        #pragma unroll 8
        for (int k=0;k<UH;k++){
            float w = U1[k*G4 + j];
            ull ww = pack2(w,w);
            #pragma unroll
            for (int p=0;p<4;p++)
                acc[p] = ffma2(ww, *(const ull*)&ht1[k*18 + 2*(pbase+p)], acc[p]);
        }
    }

    #pragma unroll
    for (int p=0;p<4;p++){
        float lo,hi; unpack2(acc[p], lo, hi);
        int b = 2*(pbase+p);
        zs[b*64 + jj]     = lo;
        zs[(b+1)*64 + jj] = hi;
    }
    __syncthreads();

    float* c_arr        = layer ? g_c1[dir]     : g_c0[dir];
    float* h_cur        = layer ? g_h1[dir][pc] : g_h0[dir][pc];
    const float* h_prev = layer ? g_h1[dir][pp] : g_h0[dir][pp];

    #pragma unroll
    for (int i=0;i<2;i++){
        int item = tid + i*128;           // 0..255 -> (b, uu)
        int b  = item >> 4;
        int uu = item & 15;
        int u  = u0 + uu;
        float zi = zs[b*64 + uu];
        float zf = zs[b*64 + 16 + uu];
        float zg = zs[b*64 + 32 + uu];
        float zo = zs[b*64 + 48 + uu];
        int idx = b*UH + u;
        float cold = c_arr[idx], hold = h_prev[idx];
        float cn = sigf(zf)*cold + sigf(zi)*tanhf(zg);
        float hn = sigf(zo)*tanhf(cn);
        int pos = dir ? (127 - t) : t;
        if (seqs[b*TT + pos] == 0){ cn = cold; hn = hold; }
        c_arr[idx] = cn;
        h_cur[idx] = hn;
        if (layer){  // store layer-1 hidden into the concat buffer (t in 0..125 always)
            int r = dir ? (b*NS + (125 - t)) : (b*NS + t);
            g_o[(size_t)r*OC + dir*UH + u] = hn;
        }
    }
}

// ---------------- projection: out[2016 x 32000] = g_o @ Wp + bp ----------------
__global__ __launch_bounds__(256) void k_proj(const float* __restrict__ Wp,
                                              const float* __restrict__ bp,
                                              float* __restrict__ Cout){
    const int m0 = blockIdx.y*128, n0 = blockIdx.x*256;
    __shared__ float As[16][128];
    __shared__ float Bs[16][256];
    const int tid = threadIdx.x;
    const int tx = tid & 15, ty = tid >> 4;

    ull acc[8][8];
    #pragma unroll
    for (int i=0;i<8;i++)
        #pragma unroll
        for (int q=0;q<8;q++) acc[i][q] = 0ull;

    for (int kt=0; kt<OC/16; kt++){      // 64 iters
        #pragma unroll
        for (int i=0;i<2;i++){
            int lin = tid + i*256;
            int row = lin>>2, c4 = lin&3;
            int r = m0 + row;
            float4 v = make_float4(0.f,0.f,0.f,0.f);
            if (r < OROWS)
                v = *(const float4*)&g_o[(size_t)r*OC + kt*16 + c4*4];
            As[c4*4+0][row]=v.x; As[c4*4+1][row]=v.y;
            As[c4*4+2][row]=v.z; As[c4*4+3][row]=v.w;
        }
        #pragma unroll
        for (int i=0;i<4;i++){
            int lin = tid + i*256;
            int kr = lin>>6, c4 = lin&63;
            *(float4*)&Bs[kr][c4*4] =
                *(const float4*)&Wp[(size_t)(kt*16+kr)*V + n0 + c4*4];
        }
        __syncthreads();
        #pragma unroll
        for (int k=0;k<16;k++){
            float a0[8];
            *(float4*)&a0[0] = *(float4*)&As[k][ty*8];
            *(float4*)&a0[4] = *(float4*)&As[k][ty*8+4];
            ull av[8];
            #pragma unroll
            for (int i=0;i<8;i++) av[i] = pack2(a0[i], a0[i]);
            ull bv[8];
            #pragma unroll
            for (int q=0;q<4;q++){
                ulonglong2 p = *(const ulonglong2*)&Bs[k][tx*16 + q*4];
                bv[2*q] = p.x; bv[2*q+1] = p.y;
            }
            #pragma unroll
            for (int i=0;i<8;i++)
                #pragma unroll
                for (int q=0;q<8;q++)
                    acc[i][q] = ffma2(av[i], bv[q], acc[i][q]);
        }
        __syncthreads();
    }
    #pragma unroll
    for (int i=0;i<8;i++){
        int r = m0 + ty*8 + i;
        if (r >= OROWS) continue;
        float* crow = Cout + (size_t)r*V + n0 + tx*16;
        #pragma unroll
        for (int q=0;q<8;q++){
            float lo,hi; unpack2(acc[i][q], lo, hi);
            int col = n0 + tx*16 + 2*q;
            float2 st; st.x = lo + bp[col]; st.y = hi + bp[col+1];
            *(float2*)&crow[2*q] = st;
        }
    }
}

// ---------------- launch ----------------
extern "C" void kernel_launch(void* const* d_in, const int* in_sizes, int n_in,
                              void* d_out, int out_size)
{
    const int*   seqs  = (const int*)  d_in[0];
    const float* embed = (const float*)d_in[1];
    const float* fW0   = (const float*)d_in[2];
    const float* fU0   = (const float*)d_in[3];
    const float* fb0   = (const float*)d_in[4];
    const float* fW1   = (const float*)d_in[5];
    const float* fU1   = (const float*)d_in[6];
    const float* fb1   = (const float*)d_in[7];
    const float* bW0   = (const float*)d_in[8];
    const float* bU0   = (const float*)d_in[9];
    const float* bb0   = (const float*)d_in[10];
    const float* bW1   = (const float*)d_in[11];
    const float* bU1   = (const float*)d_in[12];
    const float* bb1   = (const float*)d_in[13];
    const float* Wp    = (const float*)d_in[14];
    const float* bp    = (const float*)d_in[15];
    float* out = (float*)d_out;

    const int STEP_SMEM = (2*512*18 + 16*64) * 4;   // 77824 B
    cudaFuncSetAttribute(k_step, cudaFuncAttributeMaxDynamicSharedMemorySize, STEP_SMEM);

    k_init<<<(BB*UH + 255)/256, 256>>>();
    k_embed<<<(BB*TT*(D/4) + 255)/256, 256>>>(seqs, embed);

    dim3 gx(8, 16, 2);                              // N-blocks, M-blocks, dir
    k_xprep<<<gx, 256>>>(fW0, fb0, bW0, bb0);

    for (int s = 0; s <= NS; s++)                   // 127 pipelined steps
        k_step<<<128, 128, STEP_SMEM>>>(s, fU0, fW1, fU1, fb1,
                                           bU0, bW1, bU1, bb1, seqs);

    dim3 gp(V/256, 16, 1);                          // 125 x 16 blocks
    k_proj<<<gp, 256>>>(Wp, bp, out);
}

// round 2
// speedup vs baseline: 1.6978x; 1.6978x over previous
#include <cuda_runtime.h>
#include <math.h>

#define V   32000
#define D   256
#define UH  512
#define BB  16
#define TT  128
#define NS  126
#define G4  2048
#define OROWS (BB*NS)
#define OC  1024
#define NBLK 128
#define NSTEP 127

typedef unsigned long long ull;

// ---------------- device scratch ----------------
__device__ float g_emb[BB*TT*D];
__device__ float g_X[2][NS*BB*G4];          // [dir][(t*16+b)*2048 + j] = x@W0 + b0
__device__ float g_h0t[2][2][UH*BB];        // [dir][par][k*16+b]  transposed h
__device__ float g_h1t[2][2][UH*BB];
__device__ float g_o[(size_t)OROWS*OC];
__device__ float g_S[NBLK][3][8][16][16][2];// staging: [blk][m][warp][colpair][b][2]
__device__ unsigned g_cnt;
__device__ volatile unsigned g_gen;

// ---------------- f32x2 helpers ----------------
__device__ __forceinline__ ull pack2(float lo, float hi){
    ull r;
    asm("mov.b64 %0, {%1,%2};" : "=l"(r)
        : "r"(__float_as_uint(lo)), "r"(__float_as_uint(hi)));
    return r;
}
__device__ __forceinline__ void unpack2(ull v, float& lo, float& hi){
    unsigned a, b;
    asm("mov.b64 {%0,%1}, %2;" : "=r"(a), "=r"(b) : "l"(v));
    lo = __uint_as_float(a); hi = __uint_as_float(b);
}
__device__ __forceinline__ ull ffma2(ull a, ull b, ull c){
    ull r;
    asm("fma.rn.f32x2 %0, %1, %2, %3;" : "=l"(r) : "l"(a), "l"(b), "l"(c));
    return r;
}
__device__ __forceinline__ float sigf(float x){ return 1.f/(1.f + __expf(-x)); }

// ---------------- init (every replay) ----------------
__global__ void k_init(){
    int i = blockIdx.x*blockDim.x + threadIdx.x;
    int n = 2*2*UH*BB;
    if (i < n){
        ((float*)g_h0t)[i] = 0.f;
        ((float*)g_h1t)[i] = 0.f;
    }
    if (i == 0){ g_cnt = 0u; g_gen = 0u; }
}

// ---------------- embedding gather ----------------
__global__ void k_embed(const int* __restrict__ seqs, const float* __restrict__ embed){
    int i = blockIdx.x*blockDim.x + threadIdx.x;
    if (i >= BB*TT*(D/4)) return;
    int bt = i / (D/4);
    int d4 = i % (D/4);
    int tok = seqs[bt];
    float4 v = *(const float4*)&embed[(size_t)tok*D + d4*4];
    *(float4*)&g_emb[(size_t)bt*D + d4*4] = v;
}

// ---------------- X precompute GEMM ----------------
__global__ __launch_bounds__(256) void k_xprep(const float* __restrict__ fW0,
                                               const float* __restrict__ fb0,
                                               const float* __restrict__ bW0,
                                               const float* __restrict__ bb0){
    const int dir = blockIdx.z;
    const float* W    = dir ? bW0 : fW0;
    const float* bias = dir ? bb0 : fb0;
    float* out = g_X[dir];
    const int m0 = blockIdx.y*128, n0 = blockIdx.x*256;
    __shared__ float As[16][128];
    __shared__ float Bs[16][256];
    const int tid = threadIdx.x;
    const int tx = tid & 15, ty = tid >> 4;

    ull acc[8][8];
    #pragma unroll
    for (int i=0;i<8;i++)
        #pragma unroll
        for (int q=0;q<8;q++) acc[i][q] = 0ull;

    for (int kt=0; kt<16; kt++){
        #pragma unroll
        for (int i=0;i<2;i++){
            int lin = tid + i*256;
            int row = lin>>2, c4 = lin&3;
            int r = m0 + row;
            float4 v = make_float4(0.f,0.f,0.f,0.f);
            if (r < OROWS){
                int t = r>>4, b = r&15;
                int txi = dir ? (127 - t) : t;
                v = *(const float4*)&g_emb[((b<<7)+txi)*D + kt*16 + c4*4];
            }
            As[c4*4+0][row]=v.x; As[c4*4+1][row]=v.y;
            As[c4*4+2][row]=v.z; As[c4*4+3][row]=v.w;
        }
        #pragma unroll
        for (int i=0;i<4;i++){
            int lin = tid + i*256;
            int kr = lin>>6, c4 = lin&63;
            *(float4*)&Bs[kr][c4*4] =
                *(const float4*)&W[(size_t)(kt*16+kr)*G4 + n0 + c4*4];
        }
        __syncthreads();
        #pragma unroll
        for (int k=0;k<16;k++){
            float a0[8];
            *(float4*)&a0[0] = *(float4*)&As[k][ty*8];
            *(float4*)&a0[4] = *(float4*)&As[k][ty*8+4];
            ull av[8];
            #pragma unroll
            for (int i=0;i<8;i++) av[i] = pack2(a0[i], a0[i]);
            ull bv[8];
            #pragma unroll
            for (int q=0;q<4;q++){
                ulonglong2 p = *(const ulonglong2*)&Bs[k][tx*16 + q*4];
                bv[2*q] = p.x; bv[2*q+1] = p.y;
            }
            #pragma unroll
            for (int i=0;i<8;i++)
                #pragma unroll
                for (int q=0;q<8;q++)
                    acc[i][q] = ffma2(av[i], bv[q], acc[i][q]);
        }
        __syncthreads();
    }
    #pragma unroll
    for (int i=0;i<8;i++){
        int r = m0 + ty*8 + i;
        if (r >= OROWS) continue;
        float* crow = out + (size_t)r*G4 + n0 + tx*16;
        #pragma unroll
        for (int q=0;q<8;q++){
            float lo,hi; unpack2(acc[i][q], lo, hi);
            int col = n0 + tx*16 + 2*q;
            float2 st; st.x = lo + bias[col]; st.y = hi + bias[col+1];
            *(float2*)&crow[2*q] = st;
        }
    }
}

// ---------------- persistent recurrence kernel ----------------
// 128 blocks x 256 threads; block -> (dir = blk>>6, u0 = (blk&63)*8).
// SMEM: weights [3][512][32] + ht0 [512][16] + c0 [128] + c1 [128]
#define WS_FLOATS (3*512*32)
#define SMEM_FLOATS (WS_FLOATS + UH*BB + 128 + 128)

__global__ __launch_bounds__(256,1) void k_recur(
    const float* __restrict__ fU0, const float* __restrict__ fW1,
    const float* __restrict__ fU1, const float* __restrict__ fb1,
    const float* __restrict__ bU0, const float* __restrict__ bW1,
    const float* __restrict__ bU1, const float* __restrict__ bb1,
    const int*   __restrict__ seqs)
{
    extern __shared__ float sm[];
    float* ws   = sm;                      // [m][k][32]
    float* ht0s = sm + WS_FLOATS;          // [k][16]
    float* c0s  = ht0s + UH*BB;            // [uu][b]
    float* c1s  = c0s + 128;

    const int tid  = threadIdx.x;
    const int wid  = tid >> 5;
    const int lane = tid & 31;
    const int blk  = blockIdx.x;
    const int dir  = blk >> 6;
    const int u0   = (blk & 63) * 8;

    const float* Wm0 = dir ? bU0 : fU0;
    const float* Wm1 = dir ? bW1 : fW1;
    const float* Wm2 = dir ? bU1 : fU1;
    const float* b1  = dir ? bb1 : fb1;

    // ---- preload weight columns into smem (once) ----
    for (int i = tid; i < WS_FLOATS; i += 256){
        int m = i / (512*32);
        int r = i - m*(512*32);
        int k = r >> 5, c = r & 31;
        const float* Wsrc = (m==0) ? Wm0 : (m==1) ? Wm1 : Wm2;
        ws[i] = Wsrc[(size_t)k*G4 + (c>>3)*512 + u0 + (c&7)];
    }
    if (tid < 128){ c0s[tid] = 0.f; c1s[tid] = 0.f; }
    {   // zero staging (covers never-written slots)
        float4* s4 = (float4*)&g_S[blk][0][0][0][0][0];
        #pragma unroll
        for (int i=0;i<12;i++) s4[tid + i*256] = make_float4(0,0,0,0);
    }
    __syncthreads();

    const float* Xp = g_X[dir];
    const int cg = lane & 3;      // col group (8 cols)
    const int bg = lane >> 2;     // batch pair (2 b's)
    const int K0 = wid*192, K1 = K0+192;

    for (int s = 0; s < NSTEP; s++){
        // ---- fill ht0s = h0[s-1]  (par (s-1)&1 == (s+1)&1) ----
        {
            const float4* hsrc = (const float4*)g_h0t[dir][(s+1)&1];
            float4* hdst = (float4*)ht0s;
            #pragma unroll
            for (int i=0;i<8;i++){
                int idx = tid + i*256;           // 2048 float4
                hdst[idx] = __ldcg(hsrc + idx);
            }
        }
        __syncthreads();

        // ---- GEMM: warp handles global-K [K0,K1) across 3 matrices ----
        const float* h1g = g_h1t[dir][s&1];      // h1[s-2]
        #pragma unroll
        for (int m=0;m<3;m++){
            int lo = K0 - m*512; if (lo < 0) lo = 0;
            int hi = K1 - m*512; if (hi > 512) hi = 512;
            if (lo >= hi) continue;
            bool active = (m==0) ? (s < NS) : (s >= 1);
            if (!active) continue;

            ull A[4][2];
            #pragma unroll
            for (int p=0;p<4;p++){ A[p][0]=0ull; A[p][1]=0ull; }

            const float* wsm = ws + m*(512*32) + cg*8;
            if (m < 2){
                #pragma unroll 4
                for (int k=lo;k<hi;k++){
                    float2 h2 = *(const float2*)&ht0s[k*16 + 2*bg];
                    ull ha = pack2(h2.x,h2.x), hb = pack2(h2.y,h2.y);
                    ulonglong2 wa = *(const ulonglong2*)(wsm + k*32);
                    ulonglong2 wb = *(const ulonglong2*)(wsm + k*32 + 4);
                    A[0][0]=ffma2(wa.x,ha,A[0][0]); A[0][1]=ffma2(wa.x,hb,A[0][1]);
                    A[1][0]=ffma2(wa.y,ha,A[1][0]); A[1][1]=ffma2(wa.y,hb,A[1][1]);
                    A[2][0]=ffma2(wb.x,ha,A[2][0]); A[2][1]=ffma2(wb.x,hb,A[2][1]);
                    A[3][0]=ffma2(wb.y,ha,A[3][0]); A[3][1]=ffma2(wb.y,hb,A[3][1]);
                }
            } else {
                #pragma unroll 4
                for (int k=lo;k<hi;k++){
                    float2 h2 = __ldcg((const float2*)&h1g[k*16 + 2*bg]);
                    ull ha = pack2(h2.x,h2.x), hb = pack2(h2.y,h2.y);
                    ulonglong2 wa = *(const ulonglong2*)(wsm + k*32);
                    ulonglong2 wb = *(const ulonglong2*)(wsm + k*32 + 4);
                    A[0][0]=ffma2(wa.x,ha,A[0][0]); A[0][1]=ffma2(wa.x,hb,A[0][1]);
                    A[1][0]=ffma2(wa.y,ha,A[1][0]); A[1][1]=ffma2(wa.y,hb,A[1][1]);
                    A[2][0]=ffma2(wb.x,ha,A[2][0]); A[2][1]=ffma2(wb.x,hb,A[2][1]);
                    A[3][0]=ffma2(wb.y,ha,A[3][0]); A[3][1]=ffma2(wb.y,hb,A[3][1]);
                }
            }
            #pragma unroll
            for (int p=0;p<4;p++)
                #pragma unroll
                for (int j=0;j<2;j++){
                    float zl, zh; unpack2(A[p][j], zl, zh);
                    *(float2*)&g_S[blk][m][wid][cg*4+p][2*bg+j][0] = make_float2(zl, zh);
                }
        }
        __syncthreads();

        // ---- activation / state update ----
        if (tid < 128){
            if (s < NS){               // layer 0 at t = s
                int uu = tid >> 4, b = tid & 15, t = s;
                float z[4];
                #pragma unroll
                for (int g=0; g<4; g++){
                    int col = g*8 + uu, cp = col>>1, rr = col&1;
                    float a = Xp[(size_t)((t<<4)+b)*G4 + g*512 + u0 + uu];
                    #pragma unroll
                    for (int w=0; w<8; w++) a += g_S[blk][0][w][cp][b][rr];
                    z[g] = a;
                }
                float cold = c0s[tid];
                float cn = sigf(z[1])*cold + sigf(z[0])*tanhf(z[2]);
                float hn = sigf(z[3])*tanhf(cn);
                int pos = dir ? (127-t) : t;
                if (seqs[b*TT + pos] == 0){ cn = cold; hn = ht0s[(u0+uu)*16 + b]; }
                c0s[tid] = cn;
                g_h0t[dir][s&1][(u0+uu)*16 + b] = hn;
            }
        } else {
            if (s >= 1){               // layer 1 at t = s-1
                int id = tid - 128, uu = id >> 4, b = id & 15, t = s-1;
                float z[4];
                #pragma unroll
                for (int g=0; g<4; g++){
                    int col = g*8 + uu, cp = col>>1, rr = col&1;
                    float a = b1[g*512 + u0 + uu];
                    #pragma unroll
                    for (int w=0; w<8; w++)
                        a += g_S[blk][1][w][cp][b][rr] + g_S[blk][2][w][cp][b][rr];
                    z[g] = a;
                }
                float cold = c1s[id];
                float cn = sigf(z[1])*cold + sigf(z[0])*tanhf(z[2]);
                float hn = sigf(z[3])*tanhf(cn);
                int pos = dir ? (127-t) : t;
                if (seqs[b*TT + pos] == 0){
                    cn = cold;
                    hn = __ldcg(&g_h1t[dir][s&1][(u0+uu)*16 + b]);
                }
                c1s[id] = cn;
                g_h1t[dir][(s+1)&1][(u0+uu)*16 + b] = hn;    // par (s-1)&1
                int r = dir ? (b*NS + (125 - t)) : (b*NS + t);
                g_o[(size_t)r*OC + dir*UH + u0 + uu] = hn;
            }
        }

        // ---- grid barrier ----
        __threadfence();
        __syncthreads();
        if (tid == 0){
            unsigned v = atomicAdd(&g_cnt, 1u) + 1u;
            unsigned tgt = (unsigned)NBLK * (unsigned)(s+1);
            if (v == tgt) g_gen = (unsigned)(s+1);
            else while (g_gen < (unsigned)(s+1)) __nanosleep(64);
        }
        __syncthreads();
    }
}

// ---------------- projection: out[2016 x 32000] = g_o @ Wp + bp ----------------
__global__ __launch_bounds__(256) void k_proj(const float* __restrict__ Wp,
                                              const float* __restrict__ bp,
                                              float* __restrict__ Cout){
    const int m0 = blockIdx.y*128, n0 = blockIdx.x*256;
    __shared__ float As[16][128];
    __shared__ float Bs[16][256];
    const int tid = threadIdx.x;
    const int tx = tid & 15, ty = tid >> 4;

    ull acc[8][8];
    #pragma unroll
    for (int i=0;i<8;i++)
        #pragma unroll
        for (int q=0;q<8;q++) acc[i][q] = 0ull;

    for (int kt=0; kt<OC/16; kt++){
        #pragma unroll
        for (int i=0;i<2;i++){
            int lin = tid + i*256;
            int row = lin>>2, c4 = lin&3;
            int r = m0 + row;
            float4 v = make_float4(0.f,0.f,0.f,0.f);
            if (r < OROWS)
                v = *(const float4*)&g_o[(size_t)r*OC + kt*16 + c4*4];
            As[c4*4+0][row]=v.x; As[c4*4+1][row]=v.y;
            As[c4*4+2][row]=v.z; As[c4*4+3][row]=v.w;
        }
        #pragma unroll
        for (int i=0;i<4;i++){
            int lin = tid + i*256;
            int kr = lin>>6, c4 = lin&63;
            *(float4*)&Bs[kr][c4*4] =
                *(const float4*)&Wp[(size_t)(kt*16+kr)*V + n0 + c4*4];
        }
        __syncthreads();
        #pragma unroll
        for (int k=0;k<16;k++){
            float a0[8];
            *(float4*)&a0[0] = *(float4*)&As[k][ty*8];
            *(float4*)&a0[4] = *(float4*)&As[k][ty*8+4];
            ull av[8];
            #pragma unroll
            for (int i=0;i<8;i++) av[i] = pack2(a0[i], a0[i]);
            ull bv[8];
            #pragma unroll
            for (int q=0;q<4;q++){
                ulonglong2 p = *(const ulonglong2*)&Bs[k][tx*16 + q*4];
                bv[2*q] = p.x; bv[2*q+1] = p.y;
            }
            #pragma unroll
            for (int i=0;i<8;i++)
                #pragma unroll
                for (int q=0;q<8;q++)
                    acc[i][q] = ffma2(av[i], bv[q], acc[i][q]);
        }
        __syncthreads();
    }
    #pragma unroll
    for (int i=0;i<8;i++){
        int r = m0 + ty*8 + i;
        if (r >= OROWS) continue;
        float* crow = Cout + (size_t)r*V + n0 + tx*16;
        #pragma unroll
        for (int q=0;q<8;q++){
            float lo,hi; unpack2(acc[i][q], lo, hi);
            int col = n0 + tx*16 + 2*q;
            float2 st; st.x = lo + bp[col]; st.y = hi + bp[col+1];
            *(float2*)&crow[2*q] = st;
        }
    }
}

// ---------------- launch ----------------
extern "C" void kernel_launch(void* const* d_in, const int* in_sizes, int n_in,
                              void* d_out, int out_size)
{
    const int*   seqs  = (const int*)  d_in[0];
    const float* embed = (const float*)d_in[1];
    const float* fW0   = (const float*)d_in[2];
    const float* fU0   = (const float*)d_in[3];
    const float* fb0   = (const float*)d_in[4];
    const float* fW1   = (const float*)d_in[5];
    const float* fU1   = (const float*)d_in[6];
    const float* fb1   = (const float*)d_in[7];
    const float* bW0   = (const float*)d_in[8];
    const float* bU0   = (const float*)d_in[9];
    const float* bb0   = (const float*)d_in[10];
    const float* bW1   = (const float*)d_in[11];
    const float* bU1   = (const float*)d_in[12];
    const float* bb1   = (const float*)d_in[13];
    const float* Wp    = (const float*)d_in[14];
    const float* bp    = (const float*)d_in[15];
    float* out = (float*)d_out;

    const int RSMEM = SMEM_FLOATS * 4;   // 230400 B
    cudaFuncSetAttribute(k_recur, cudaFuncAttributeMaxDynamicSharedMemorySize, RSMEM);

    k_init<<<(2*2*UH*BB + 255)/256, 256>>>();
    k_embed<<<(BB*TT*(D/4) + 255)/256, 256>>>(seqs, embed);

    dim3 gx(8, 16, 2);
    k_xprep<<<gx, 256>>>(fW0, fb0, bW0, bb0);

    k_recur<<<NBLK, 256, RSMEM>>>(fU0, fW1, fU1, fb1, bU0, bW1, bU1, bb1, seqs);

    dim3 gp(V/256, 16, 1);
    k_proj<<<gp, 256>>>(Wp, bp, out);
}

// round 3
// speedup vs baseline: 1.8554x; 1.0929x over previous
#include <cuda_runtime.h>
#include <math.h>

#define V   32000
#define D   256
#define UH  512
#define BB  16
#define TT  128
#define NS  126
#define G4  2048
#define OROWS (BB*NS)
#define OC  1024
#define NBLK 128
#define NSTEP 127

typedef unsigned long long ull;

// ---------------- device scratch ----------------
__device__ float g_emb[BB*TT*D];
__device__ float g_X[2][NS*BB*G4];          // [dir][(t*16+b)*2048 + j]
__device__ float g_h0t[2][2][UH*BB];        // [dir][par][k*16+b]
__device__ float g_h1t[2][2][UH*BB];
__device__ float g_o[(size_t)OROWS*OC];
__device__ unsigned g_cnt;
__device__ volatile unsigned g_gen;

// ---------------- f32x2 helpers ----------------
__device__ __forceinline__ ull pack2(float lo, float hi){
    ull r;
    asm("mov.b64 %0, {%1,%2};" : "=l"(r)
        : "r"(__float_as_uint(lo)), "r"(__float_as_uint(hi)));
    return r;
}
__device__ __forceinline__ void unpack2(ull v, float& lo, float& hi){
    unsigned a, b;
    asm("mov.b64 {%0,%1}, %2;" : "=r"(a), "=r"(b) : "l"(v));
    lo = __uint_as_float(a); hi = __uint_as_float(b);
}
__device__ __forceinline__ ull ffma2(ull a, ull b, ull c){
    ull r;
    asm("fma.rn.f32x2 %0, %1, %2, %3;" : "=l"(r) : "l"(a), "l"(b), "l"(c));
    return r;
}
__device__ __forceinline__ float sigf(float x){ return 1.f/(1.f + __expf(-x)); }
__device__ __forceinline__ float tanhfast(float x){ return 2.f/(1.f + __expf(-2.f*x)) - 1.f; }

// ---------------- init (every replay) ----------------
__global__ void k_init(){
    int i = blockIdx.x*blockDim.x + threadIdx.x;
    int n = 2*2*UH*BB;
    if (i < n){
        ((float*)g_h0t)[i] = 0.f;
        ((float*)g_h1t)[i] = 0.f;
    }
    if (i == 0){ g_cnt = 0u; g_gen = 0u; }
}

// ---------------- embedding gather ----------------
__global__ void k_embed(const int* __restrict__ seqs, const float* __restrict__ embed){
    int i = blockIdx.x*blockDim.x + threadIdx.x;
    if (i >= BB*TT*(D/4)) return;
    int bt = i / (D/4);
    int d4 = i % (D/4);
    int tok = seqs[bt];
    float4 v = *(const float4*)&embed[(size_t)tok*D + d4*4];
    *(float4*)&g_emb[(size_t)bt*D + d4*4] = v;
}

// ---------------- X precompute GEMM ----------------
__global__ __launch_bounds__(256) void k_xprep(const float* __restrict__ fW0,
                                               const float* __restrict__ fb0,
                                               const float* __restrict__ bW0,
                                               const float* __restrict__ bb0){
    const int dir = blockIdx.z;
    const float* W    = dir ? bW0 : fW0;
    const float* bias = dir ? bb0 : fb0;
    float* out = g_X[dir];
    const int m0 = blockIdx.y*128, n0 = blockIdx.x*256;
    __shared__ float As[16][128];
    __shared__ float Bs[16][256];
    const int tid = threadIdx.x;
    const int tx = tid & 15, ty = tid >> 4;

    ull acc[8][8];
    #pragma unroll
    for (int i=0;i<8;i++)
        #pragma unroll
        for (int q=0;q<8;q++) acc[i][q] = 0ull;

    for (int kt=0; kt<16; kt++){
        #pragma unroll
        for (int i=0;i<2;i++){
            int lin = tid + i*256;
            int row = lin>>2, c4 = lin&3;
            int r = m0 + row;
            float4 v = make_float4(0.f,0.f,0.f,0.f);
            if (r < OROWS){
                int t = r>>4, b = r&15;
                int txi = dir ? (127 - t) : t;
                v = *(const float4*)&g_emb[((b<<7)+txi)*D + kt*16 + c4*4];
            }
            As[c4*4+0][row]=v.x; As[c4*4+1][row]=v.y;
            As[c4*4+2][row]=v.z; As[c4*4+3][row]=v.w;
        }
        #pragma unroll
        for (int i=0;i<4;i++){
            int lin = tid + i*256;
            int kr = lin>>6, c4 = lin&63;
            *(float4*)&Bs[kr][c4*4] =
                *(const float4*)&W[(size_t)(kt*16+kr)*G4 + n0 + c4*4];
        }
        __syncthreads();
        #pragma unroll
        for (int k=0;k<16;k++){
            float a0[8];
            *(float4*)&a0[0] = *(float4*)&As[k][ty*8];
            *(float4*)&a0[4] = *(float4*)&As[k][ty*8+4];
            ull av[8];
            #pragma unroll
            for (int i=0;i<8;i++) av[i] = pack2(a0[i], a0[i]);
            ull bv[8];
            #pragma unroll
            for (int q=0;q<4;q++){
                ulonglong2 p = *(const ulonglong2*)&Bs[k][tx*16 + q*4];
                bv[2*q] = p.x; bv[2*q+1] = p.y;
            }
            #pragma unroll
            for (int i=0;i<8;i++)
                #pragma unroll
                for (int q=0;q<8;q++)
                    acc[i][q] = ffma2(av[i], bv[q], acc[i][q]);
        }
        __syncthreads();
    }
    #pragma unroll
    for (int i=0;i<8;i++){
        int r = m0 + ty*8 + i;
        if (r >= OROWS) continue;
        float* crow = out + (size_t)r*G4 + n0 + tx*16;
        #pragma unroll
        for (int q=0;q<8;q++){
            float lo,hi; unpack2(acc[i][q], lo, hi);
            int col = n0 + tx*16 + 2*q;
            float2 st; st.x = lo + bias[col]; st.y = hi + bias[col+1];
            *(float2*)&crow[2*q] = st;
        }
    }
}

// ---------------- persistent recurrence ----------------
// 128 blocks x 256 threads. blk -> dir = blk>>6, u0 = (blk&63)*8.
// SMEM: ws01 [512][64] (U0|W1 cols) 128KB, ht0 32KB, ht1 32KB,
//       zpart [4][48][16][2] 24KB, c-state 1KB  -> 222208 B
#define WS01_FL   (512*64)
#define HT_FL     (UH*BB)
#define ZP_FL     (4*48*16*2)
#define RSMEM_FL  (WS01_FL + 2*HT_FL + ZP_FL + 256)

__global__ __launch_bounds__(256,1) void k_recur(
    const float* __restrict__ fU0, const float* __restrict__ fW1,
    const float* __restrict__ fU1, const float* __restrict__ fb1,
    const float* __restrict__ bU0, const float* __restrict__ bW1,
    const float* __restrict__ bU1, const float* __restrict__ bb1,
    const int*   __restrict__ seqs)
{
    extern __shared__ float sm[];
    float* ws01 = sm;                       // [k][64]
    float* ht0s = sm + WS01_FL;             // [k][16]
    float* ht1s = ht0s + HT_FL;
    float* zpf  = ht1s + HT_FL;             // [4][48][16][2]
    float* c0s  = zpf + ZP_FL;              // [128]
    float* c1s  = c0s + 128;
    ull*   zpu  = (ull*)zpf;                // [(q*48+cp)*16 + b]

    const int tid  = threadIdx.x;
    const int wid  = tid >> 5;
    const int lane = tid & 31;
    const int blk  = blockIdx.x;
    const int dir  = blk >> 6;
    const int u0   = (blk & 63) * 8;

    const float* U0 = dir ? bU0 : fU0;
    const float* W1 = dir ? bW1 : fW1;
    const float* U1 = dir ? bU1 : fU1;
    const float* b1 = dir ? bb1 : fb1;
    const float* Xp = g_X[dir];

    // preload U0|W1 column slices: ws01[k*64 + j], j<32 -> U0, j>=32 -> W1
    for (int idx = tid; idx < WS01_FL; idx += 256){
        int k = idx >> 6, j = idx & 63;
        const float* Wsrc = (j < 32) ? U0 : W1;
        int jj = j & 31;
        ws01[idx] = Wsrc[(size_t)k*G4 + (jj>>3)*512 + u0 + (jj&7)];
    }
    if (tid < 128){ c0s[tid] = 0.f; c1s[tid] = 0.f; }
    __syncthreads();

    const int q  = wid & 3;            // k-quarter
    const int hf = wid >> 2;           // col-half
    const int cg = lane & 3;
    const int bg = lane >> 2;
    const int k0 = q * 128;

    const float* wsA = ws01 + (size_t)k0*64 + hf*32 + cg*8;
    const float* hA  = ht0s + k0*16 + 2*bg;
    const float* hB  = ht1s + k0*16 + 2*bg;
    const int gB = hf*2 + (cg>>1);
    const float* wBg = U1 + (size_t)k0*G4 + gB*512 + u0 + (cg&1)*4;

    for (int s = 0; s < NSTEP; s++){
        // ---- stage h0[s-1], h1[s-2] into smem ----
        {
            const float4* s0 = (const float4*)g_h0t[dir][(s+1)&1];
            const float4* s1 = (const float4*)g_h1t[dir][s&1];
            float4* d0 = (float4*)ht0s;
            float4* d1 = (float4*)ht1s;
            #pragma unroll
            for (int i=0;i<8;i++){ int ix = tid + i*256; d0[ix] = __ldcg(s0+ix); }
            #pragma unroll
            for (int i=0;i<8;i++){ int ix = tid + i*256; d1[ix] = __ldcg(s1+ix); }
        }
        __syncthreads();

        // ---- GEMM ----
        ull aA[4][2], aB[2][2];
        #pragma unroll
        for (int i=0;i<4;i++){ aA[i][0]=0ull; aA[i][1]=0ull; }
        #pragma unroll
        for (int i=0;i<2;i++){ aB[i][0]=0ull; aB[i][1]=0ull; }

        float4 wreg[8], wnxt[8];
        #pragma unroll
        for (int j=0;j<8;j++)
            wreg[j] = __ldcg((const float4*)(wBg + (size_t)j*G4));

        #pragma unroll 2
        for (int c=0;c<16;c++){
            if (c < 15){
                #pragma unroll
                for (int j=0;j<8;j++)
                    wnxt[j] = __ldcg((const float4*)(wBg + (size_t)((c+1)*8+j)*G4));
            }
            // phase A: U0|W1 from smem, h0 from smem
            #pragma unroll
            for (int j=0;j<8;j++){
                int k = c*8 + j;
                float2 h2 = *(const float2*)(hA + k*16);
                ull hx = pack2(h2.x,h2.x), hy = pack2(h2.y,h2.y);
                ulonglong2 wa = *(const ulonglong2*)(wsA + (size_t)k*64);
                ulonglong2 wb = *(const ulonglong2*)(wsA + (size_t)k*64 + 4);
                aA[0][0]=ffma2(wa.x,hx,aA[0][0]); aA[0][1]=ffma2(wa.x,hy,aA[0][1]);
                aA[1][0]=ffma2(wa.y,hx,aA[1][0]); aA[1][1]=ffma2(wa.y,hy,aA[1][1]);
                aA[2][0]=ffma2(wb.x,hx,aA[2][0]); aA[2][1]=ffma2(wb.x,hy,aA[2][1]);
                aA[3][0]=ffma2(wb.y,hx,aA[3][0]); aA[3][1]=ffma2(wb.y,hy,aA[3][1]);
            }
            // phase B: U1 from prefetched regs, h1 from smem
            #pragma unroll
            for (int j=0;j<8;j++){
                int k = c*8 + j;
                float2 h2 = *(const float2*)(hB + k*16);
                ull hx = pack2(h2.x,h2.x), hy = pack2(h2.y,h2.y);
                ull w0 = pack2(wreg[j].x, wreg[j].y);
                ull w1 = pack2(wreg[j].z, wreg[j].w);
                aB[0][0]=ffma2(w0,hx,aB[0][0]); aB[0][1]=ffma2(w0,hy,aB[0][1]);
                aB[1][0]=ffma2(w1,hx,aB[1][0]); aB[1][1]=ffma2(w1,hy,aB[1][1]);
            }
            #pragma unroll
            for (int j=0;j<8;j++) wreg[j] = wnxt[j];
        }

        // ---- write partials to smem ----
        #pragma unroll
        for (int i=0;i<4;i++){
            int cp = hf*16 + cg*4 + i;
            zpu[(q*48 + cp)*16 + 2*bg + 0] = aA[i][0];
            zpu[(q*48 + cp)*16 + 2*bg + 1] = aA[i][1];
        }
        #pragma unroll
        for (int i=0;i<2;i++){
            int cp = 32 + hf*8 + cg*2 + i;
            zpu[(q*48 + cp)*16 + 2*bg + 0] = aB[i][0];
            zpu[(q*48 + cp)*16 + 2*bg + 1] = aB[i][1];
        }
        __syncthreads();

        // ---- activation / state update ----
        {
            int layer = tid >> 7, id = tid & 127;
            int uu = id >> 4, b = id & 15;
            if (layer == 0){
                if (s < NS){
                    int t = s;
                    float z[4];
                    #pragma unroll
                    for (int g=0; g<4; g++){
                        int x = g*8 + uu, cp = x>>1, par = x&1;
                        float a = Xp[(size_t)((t<<4)+b)*G4 + g*512 + u0 + uu];
                        #pragma unroll
                        for (int qq=0; qq<4; qq++)
                            a += zpf[(((qq*48 + cp)*16) + b)*2 + par];
                        z[g] = a;
                    }
                    float cold = c0s[id];
                    float cn = sigf(z[1])*cold + sigf(z[0])*tanhfast(z[2]);
                    float hn = sigf(z[3])*tanhfast(cn);
                    int pos = dir ? (127 - t) : t;
                    if (seqs[b*TT + pos] == 0){
                        cn = cold; hn = ht0s[(u0+uu)*16 + b];
                    }
                    c0s[id] = cn;
                    g_h0t[dir][s&1][(u0+uu)*16 + b] = hn;
                }
            } else {
                if (s >= 1){
                    int t = s - 1;
                    float z[4];
                    #pragma unroll
                    for (int g=0; g<4; g++){
                        int x = g*8 + uu, par = x&1;
                        int cp1 = 16 + (x>>1), cp2 = 32 + (x>>1);
                        float a = b1[g*512 + u0 + uu];
                        #pragma unroll
                        for (int qq=0; qq<4; qq++)
                            a += zpf[(((qq*48 + cp1)*16) + b)*2 + par]
                               + zpf[(((qq*48 + cp2)*16) + b)*2 + par];
                        z[g] = a;
                    }
                    float cold = c1s[id];
                    float cn = sigf(z[1])*cold + sigf(z[0])*tanhfast(z[2]);
                    float hn = sigf(z[3])*tanhfast(cn);
                    int pos = dir ? (127 - t) : t;
                    if (seqs[b*TT + pos] == 0){
                        cn = cold; hn = ht1s[(u0+uu)*16 + b];
                    }
                    c1s[id] = cn;
                    g_h1t[dir][(s+1)&1][(u0+uu)*16 + b] = hn;
                    int r = dir ? (b*NS + (125 - t)) : (b*NS + t);
                    g_o[(size_t)r*OC + dir*UH + u0 + uu] = hn;
                }
            }
        }

        // ---- grid barrier ----
        __threadfence();
        __syncthreads();
        if (tid == 0){
            unsigned v = atomicAdd(&g_cnt, 1u) + 1u;
            unsigned tgt = (unsigned)NBLK * (unsigned)(s+1);
            if (v == tgt) g_gen = (unsigned)(s+1);
            else while (g_gen < (unsigned)(s+1)) { }
        }
        __syncthreads();
    }
}

// ---------------- projection: out[2016 x 32000] = g_o @ Wp + bp ----------------
__global__ __launch_bounds__(256) void k_proj(const float* __restrict__ Wp,
                                              const float* __restrict__ bp,
                                              float* __restrict__ Cout){
    const int m0 = blockIdx.y*128, n0 = blockIdx.x*256;
    __shared__ float As[16][128];
    __shared__ float Bs[16][256];
    const int tid = threadIdx.x;
    const int tx = tid & 15, ty = tid >> 4;

    ull acc[8][8];
    #pragma unroll
    for (int i=0;i<8;i++)
        #pragma unroll
        for (int q=0;q<8;q++) acc[i][q] = 0ull;

    for (int kt=0; kt<OC/16; kt++){
        #pragma unroll
        for (int i=0;i<2;i++){
            int lin = tid + i*256;
            int row = lin>>2, c4 = lin&3;
            int r = m0 + row;
            float4 v = make_float4(0.f,0.f,0.f,0.f);
            if (r < OROWS)
                v = *(const float4*)&g_o[(size_t)r*OC + kt*16 + c4*4];
            As[c4*4+0][row]=v.x; As[c4*4+1][row]=v.y;
            As[c4*4+2][row]=v.z; As[c4*4+3][row]=v.w;
        }
        #pragma unroll
        for (int i=0;i<4;i++){
            int lin = tid + i*256;
            int kr = lin>>6, c4 = lin&63;
            *(float4*)&Bs[kr][c4*4] =
                *(const float4*)&Wp[(size_t)(kt*16+kr)*V + n0 + c4*4];
        }
        __syncthreads();
        #pragma unroll
        for (int k=0;k<16;k++){
            float a0[8];
            *(float4*)&a0[0] = *(float4*)&As[k][ty*8];
            *(float4*)&a0[4] = *(float4*)&As[k][ty*8+4];
            ull av[8];
            #pragma unroll
            for (int i=0;i<8;i++) av[i] = pack2(a0[i], a0[i]);
            ull bv[8];
            #pragma unroll
            for (int q=0;q<4;q++){
                ulonglong2 p = *(const ulonglong2*)&Bs[k][tx*16 + q*4];
                bv[2*q] = p.x; bv[2*q+1] = p.y;
            }
            #pragma unroll
            for (int i=0;i<8;i++)
                #pragma unroll
                for (int q=0;q<8;q++)
                    acc[i][q] = ffma2(av[i], bv[q], acc[i][q]);
        }
        __syncthreads();
    }
    #pragma unroll
    for (int i=0;i<8;i++){
        int r = m0 + ty*8 + i;
        if (r >= OROWS) continue;
        float* crow = Cout + (size_t)r*V + n0 + tx*16;
        #pragma unroll
        for (int q=0;q<8;q++){
            float lo,hi; unpack2(acc[i][q], lo, hi);
            int col = n0 + tx*16 + 2*q;
            float2 st; st.x = lo + bp[col]; st.y = hi + bp[col+1];
            *(float2*)&crow[2*q] = st;
        }
    }
}

// ---------------- launch ----------------
extern "C" void kernel_launch(void* const* d_in, const int* in_sizes, int n_in,
                              void* d_out, int out_size)
{
    const int*   seqs  = (const int*)  d_in[0];
    const float* embed = (const float*)d_in[1];
    const float* fW0   = (const float*)d_in[2];
    const float* fU0   = (const float*)d_in[3];
    const float* fb0   = (const float*)d_in[4];
    const float* fW1   = (const float*)d_in[5];
    const float* fU1   = (const float*)d_in[6];
    const float* fb1   = (const float*)d_in[7];
    const float* bW0   = (const float*)d_in[8];
    const float* bU0   = (const float*)d_in[9];
    const float* bb0   = (const float*)d_in[10];
    const float* bW1   = (const float*)d_in[11];
    const float* bU1   = (const float*)d_in[12];
    const float* bb1   = (const float*)d_in[13];
    const float* Wp    = (const float*)d_in[14];
    const float* bp    = (const float*)d_in[15];
    float* out = (float*)d_out;

    const int RSMEM = RSMEM_FL * 4;   // 222208 B
    cudaFuncSetAttribute(k_recur, cudaFuncAttributeMaxDynamicSharedMemorySize, RSMEM);

    k_init<<<(2*2*UH*BB + 255)/256, 256>>>();
    k_embed<<<(BB*TT*(D/4) + 255)/256, 256>>>(seqs, embed);

    dim3 gx(8, 16, 2);
    k_xprep<<<gx, 256>>>(fW0, fb0, bW0, bb0);

    k_recur<<<NBLK, 256, RSMEM>>>(fU0, fW1, fU1, fb1, bU0, bW1, bU1, bb1, seqs);

    dim3 gp(V/256, 16, 1);
    k_proj<<<gp, 256>>>(Wp, bp, out);
}

// round 6
// speedup vs baseline: 4.1127x; 2.2165x over previous
#include <cuda_runtime.h>
#include <cuda_fp16.h>
#include <cstdint>
#include <math.h>

#define V   32000
#define D   256
#define UH  512
#define BB  16
#define TT  128
#define NS  126
#define G4  2048
#define OROWS (BB*NS)
#define OC  1024
#define NBLK 128
#define NSTEP 127

typedef unsigned long long ull;

// ---------------- device scratch ----------------
__device__ float g_emb[BB*TT*D];
__device__ float g_X[2][NS*BB*G4];
__device__ float g_h0t[2][2][UH*BB];
__device__ float g_h1t[2][2][UH*BB];
__device__ float g_o[(size_t)OROWS*OC];
__device__ unsigned g_cnt;
__device__ volatile unsigned g_gen;
// fp16 split operands for HMMA projection
__device__ __half A_h[(size_t)2048*2048];     // [m][ hi(1024) | resid(1024) ]
__device__ __half B_h[(size_t)32000*1024];    // [n][k]  (Wp^T, fp16)

// ---------------- f32x2 helpers ----------------
__device__ __forceinline__ ull pack2(float lo, float hi){
    ull r;
    asm("mov.b64 %0, {%1,%2};" : "=l"(r)
        : "r"(__float_as_uint(lo)), "r"(__float_as_uint(hi)));
    return r;
}
__device__ __forceinline__ void unpack2(ull v, float& lo, float& hi){
    unsigned a, b;
    asm("mov.b64 {%0,%1}, %2;" : "=r"(a), "=r"(b) : "l"(v));
    lo = __uint_as_float(a); hi = __uint_as_float(b);
}
__device__ __forceinline__ ull ffma2(ull a, ull b, ull c){
    ull r;
    asm("fma.rn.f32x2 %0, %1, %2, %3;" : "=l"(r) : "l"(a), "l"(b), "l"(c));
    return r;
}
__device__ __forceinline__ float sigf(float x){ return 1.f/(1.f + __expf(-x)); }
__device__ __forceinline__ float tanhfast(float x){ return 2.f/(1.f + __expf(-2.f*x)) - 1.f; }

// ---------------- arch-neutral PTX helpers (sm_80-class only!) ----------------
__device__ __forceinline__ uint32_t smem_u32(const void* p){
    uint32_t a;
    asm("{ .reg .u64 t; cvta.to.shared.u64 t, %1; cvt.u32.u64 %0, t; }" : "=r"(a) : "l"(p));
    return a;
}
__device__ __forceinline__ void cpa16(uint32_t s, const void* g){
    asm volatile("cp.async.cg.shared.global [%0], [%1], 16;" :: "r"(s), "l"(g) : "memory");
}
#define CPA_COMMIT() asm volatile("cp.async.commit_group;" ::: "memory")
#define CPA_WAIT1()  asm volatile("cp.async.wait_group 1;" ::: "memory")
#define CPA_WAIT0()  asm volatile("cp.async.wait_group 0;" ::: "memory")

#define LDSM_X4(r0,r1,r2,r3,addr) \
    asm volatile("ldmatrix.sync.aligned.m8n8.x4.shared.b16 {%0,%1,%2,%3}, [%4];" \
        : "=r"(r0), "=r"(r1), "=r"(r2), "=r"(r3) : "r"(addr))
#define LDSM_X2(r0,r1,addr) \
    asm volatile("ldmatrix.sync.aligned.m8n8.x2.shared.b16 {%0,%1}, [%2];" \
        : "=r"(r0), "=r"(r1) : "r"(addr))
#define MMA16816(c,a,b) \
    asm volatile("mma.sync.aligned.m16n8k16.row.col.f32.f16.f16.f32 " \
        "{%0,%1,%2,%3}, {%4,%5,%6,%7}, {%8,%9}, {%0,%1,%2,%3};" \
        : "+f"((c)[0]), "+f"((c)[1]), "+f"((c)[2]), "+f"((c)[3]) \
        : "r"((a)[0]), "r"((a)[1]), "r"((a)[2]), "r"((a)[3]), \
          "r"((b)[0]), "r"((b)[1]))

// ---------------- init (every replay) ----------------
__global__ void k_init(){
    int i = blockIdx.x*blockDim.x + threadIdx.x;
    int n = 2*2*UH*BB;
    if (i < n){
        ((float*)g_h0t)[i] = 0.f;
        ((float*)g_h1t)[i] = 0.f;
    }
    if (i == 0){ g_cnt = 0u; g_gen = 0u; }
}

// ---------------- embedding gather ----------------
__global__ void k_embed(const int* __restrict__ seqs, const float* __restrict__ embed){
    int i = blockIdx.x*blockDim.x + threadIdx.x;
    if (i >= BB*TT*(D/4)) return;
    int bt = i / (D/4);
    int d4 = i % (D/4);
    int tok = seqs[bt];
    float4 v = *(const float4*)&embed[(size_t)tok*D + d4*4];
    *(float4*)&g_emb[(size_t)bt*D + d4*4] = v;
}

// ---------------- X precompute GEMM (fp32 FFMA2) ----------------
__global__ __launch_bounds__(256) void k_xprep(const float* __restrict__ fW0,
                                               const float* __restrict__ fb0,
                                               const float* __restrict__ bW0,
                                               const float* __restrict__ bb0){
    const int dir = blockIdx.z;
    const float* W    = dir ? bW0 : fW0;
    const float* bias = dir ? bb0 : fb0;
    float* out = g_X[dir];
    const int m0 = blockIdx.y*128, n0 = blockIdx.x*256;
    __shared__ float As[16][128];
    __shared__ float Bs[16][256];
    const int tid = threadIdx.x;
    const int tx = tid & 15, ty = tid >> 4;

    ull acc[8][8];
    #pragma unroll
    for (int i=0;i<8;i++)
        #pragma unroll
        for (int q=0;q<8;q++) acc[i][q] = 0ull;

    for (int kt=0; kt<16; kt++){
        #pragma unroll
        for (int i=0;i<2;i++){
            int lin = tid + i*256;
            int row = lin>>2, c4 = lin&3;
            int r = m0 + row;
            float4 v = make_float4(0.f,0.f,0.f,0.f);
            if (r < OROWS){
                int t = r>>4, b = r&15;
                int txi = dir ? (127 - t) : t;
                v = *(const float4*)&g_emb[((b<<7)+txi)*D + kt*16 + c4*4];
            }
            As[c4*4+0][row]=v.x; As[c4*4+1][row]=v.y;
            As[c4*4+2][row]=v.z; As[c4*4+3][row]=v.w;
        }
        #pragma unroll
        for (int i=0;i<4;i++){
            int lin = tid + i*256;
            int kr = lin>>6, c4 = lin&63;
            *(float4*)&Bs[kr][c4*4] =
                *(const float4*)&W[(size_t)(kt*16+kr)*G4 + n0 + c4*4];
        }
        __syncthreads();
        #pragma unroll
        for (int k=0;k<16;k++){
            float a0[8];
            *(float4*)&a0[0] = *(float4*)&As[k][ty*8];
            *(float4*)&a0[4] = *(float4*)&As[k][ty*8+4];
            ull av[8];
            #pragma unroll
            for (int i=0;i<8;i++) av[i] = pack2(a0[i], a0[i]);
            ull bv[8];
            #pragma unroll
            for (int q=0;q<4;q++){
                ulonglong2 p = *(const ulonglong2*)&Bs[k][tx*16 + q*4];
                bv[2*q] = p.x; bv[2*q+1] = p.y;
            }
            #pragma unroll
            for (int i=0;i<8;i++)
                #pragma unroll
                for (int q=0;q<8;q++)
                    acc[i][q] = ffma2(av[i], bv[q], acc[i][q]);
        }
        __syncthreads();
    }
    #pragma unroll
    for (int i=0;i<8;i++){
        int r = m0 + ty*8 + i;
        if (r >= OROWS) continue;
        float* crow = out + (size_t)r*G4 + n0 + tx*16;
        #pragma unroll
        for (int q=0;q<8;q++){
            float lo,hi; unpack2(acc[i][q], lo, hi);
            int col = n0 + tx*16 + 2*q;
            float2 st; st.x = lo + bias[col]; st.y = hi + bias[col+1];
            *(float2*)&crow[2*q] = st;
        }
    }
}

// ---------------- persistent recurrence (R3, unchanged) ----------------
#define WS01_FL   (512*64)
#define HT_FL     (UH*BB)
#define ZP_FL     (4*48*16*2)
#define RSMEM_FL  (WS01_FL + 2*HT_FL + ZP_FL + 256)

__global__ __launch_bounds__(256,1) void k_recur(
    const float* __restrict__ fU0, const float* __restrict__ fW1,
    const float* __restrict__ fU1, const float* __restrict__ fb1,
    const float* __restrict__ bU0, const float* __restrict__ bW1,
    const float* __restrict__ bU1, const float* __restrict__ bb1,
    const int*   __restrict__ seqs)
{
    extern __shared__ float sm[];
    float* ws01 = sm;
    float* ht0s = sm + WS01_FL;
    float* ht1s = ht0s + HT_FL;
    float* zpf  = ht1s + HT_FL;
    float* c0s  = zpf + ZP_FL;
    float* c1s  = c0s + 128;
    ull*   zpu  = (ull*)zpf;

    const int tid  = threadIdx.x;
    const int wid  = tid >> 5;
    const int lane = tid & 31;
    const int blk  = blockIdx.x;
    const int dir  = blk >> 6;
    const int u0   = (blk & 63) * 8;

    const float* U0 = dir ? bU0 : fU0;
    const float* W1 = dir ? bW1 : fW1;
    const float* U1 = dir ? bU1 : fU1;
    const float* b1 = dir ? bb1 : fb1;
    const float* Xp = g_X[dir];

    for (int idx = tid; idx < WS01_FL; idx += 256){
        int k = idx >> 6, j = idx & 63;
        const float* Wsrc = (j < 32) ? U0 : W1;
        int jj = j & 31;
        ws01[idx] = Wsrc[(size_t)k*G4 + (jj>>3)*512 + u0 + (jj&7)];
    }
    if (tid < 128){ c0s[tid] = 0.f; c1s[tid] = 0.f; }
    __syncthreads();

    const int q  = wid & 3;
    const int hf = wid >> 2;
    const int cg = lane & 3;
    const int bg = lane >> 2;
    const int k0 = q * 128;

    const float* wsA = ws01 + (size_t)k0*64 + hf*32 + cg*8;
    const float* hA  = ht0s + k0*16 + 2*bg;
    const float* hB  = ht1s + k0*16 + 2*bg;
    const int gB = hf*2 + (cg>>1);
    const float* wBg = U1 + (size_t)k0*G4 + gB*512 + u0 + (cg&1)*4;

    for (int s = 0; s < NSTEP; s++){
        {
            const float4* s0 = (const float4*)g_h0t[dir][(s+1)&1];
            const float4* s1 = (const float4*)g_h1t[dir][s&1];
            float4* d0 = (float4*)ht0s;
            float4* d1 = (float4*)ht1s;
            #pragma unroll
            for (int i=0;i<8;i++){ int ix = tid + i*256; d0[ix] = __ldcg(s0+ix); }
            #pragma unroll
            for (int i=0;i<8;i++){ int ix = tid + i*256; d1[ix] = __ldcg(s1+ix); }
        }
        __syncthreads();

        ull aA[4][2], aB[2][2];
        #pragma unroll
        for (int i=0;i<4;i++){ aA[i][0]=0ull; aA[i][1]=0ull; }
        #pragma unroll
        for (int i=0;i<2;i++){ aB[i][0]=0ull; aB[i][1]=0ull; }

        float4 wreg[8], wnxt[8];
        #pragma unroll
        for (int j=0;j<8;j++)
            wreg[j] = __ldcg((const float4*)(wBg + (size_t)j*G4));

        #pragma unroll 2
        for (int c=0;c<16;c++){
            if (c < 15){
                #pragma unroll
                for (int j=0;j<8;j++)
                    wnxt[j] = __ldcg((const float4*)(wBg + (size_t)((c+1)*8+j)*G4));
            }
            #pragma unroll
            for (int j=0;j<8;j++){
                int k = c*8 + j;
                float2 h2 = *(const float2*)(hA + k*16);
                ull hx = pack2(h2.x,h2.x), hy = pack2(h2.y,h2.y);
                ulonglong2 wa = *(const ulonglong2*)(wsA + (size_t)k*64);
                ulonglong2 wb = *(const ulonglong2*)(wsA + (size_t)k*64 + 4);
                aA[0][0]=ffma2(wa.x,hx,aA[0][0]); aA[0][1]=ffma2(wa.x,hy,aA[0][1]);
                aA[1][0]=ffma2(wa.y,hx,aA[1][0]); aA[1][1]=ffma2(wa.y,hy,aA[1][1]);
                aA[2][0]=ffma2(wb.x,hx,aA[2][0]); aA[2][1]=ffma2(wb.x,hy,aA[2][1]);
                aA[3][0]=ffma2(wb.y,hx,aA[3][0]); aA[3][1]=ffma2(wb.y,hy,aA[3][1]);
            }
            #pragma unroll
            for (int j=0;j<8;j++){
                int k = c*8 + j;
                float2 h2 = *(const float2*)(hB + k*16);
                ull hx = pack2(h2.x,h2.x), hy = pack2(h2.y,h2.y);
                ull w0 = pack2(wreg[j].x, wreg[j].y);
                ull w1 = pack2(wreg[j].z, wreg[j].w);
                aB[0][0]=ffma2(w0,hx,aB[0][0]); aB[0][1]=ffma2(w0,hy,aB[0][1]);
                aB[1][0]=ffma2(w1,hx,aB[1][0]); aB[1][1]=ffma2(w1,hy,aB[1][1]);
            }
            #pragma unroll
            for (int j=0;j<8;j++) wreg[j] = wnxt[j];
        }

        #pragma unroll
        for (int i=0;i<4;i++){
            int cp = hf*16 + cg*4 + i;
            zpu[(q*48 + cp)*16 + 2*bg + 0] = aA[i][0];
            zpu[(q*48 + cp)*16 + 2*bg + 1] = aA[i][1];
        }
        #pragma unroll
        for (int i=0;i<2;i++){
            int cp = 32 + hf*8 + cg*2 + i;
            zpu[(q*48 + cp)*16 + 2*bg + 0] = aB[i][0];
            zpu[(q*48 + cp)*16 + 2*bg + 1] = aB[i][1];
        }
        __syncthreads();

        {
            int layer = tid >> 7, id = tid & 127;
            int uu = id >> 4, b = id & 15;
            if (layer == 0){
                if (s < NS){
                    int t = s;
                    float z[4];
                    #pragma unroll
                    for (int g=0; g<4; g++){
                        int x = g*8 + uu, cp = x>>1, par = x&1;
                        float a = Xp[(size_t)((t<<4)+b)*G4 + g*512 + u0 + uu];
                        #pragma unroll
                        for (int qq=0; qq<4; qq++)
                            a += zpf[(((qq*48 + cp)*16) + b)*2 + par];
                        z[g] = a;
                    }
                    float cold = c0s[id];
                    float cn = sigf(z[1])*cold + sigf(z[0])*tanhfast(z[2]);
                    float hn = sigf(z[3])*tanhfast(cn);
                    int pos = dir ? (127 - t) : t;
                    if (seqs[b*TT + pos] == 0){
                        cn = cold; hn = ht0s[(u0+uu)*16 + b];
                    }
                    c0s[id] = cn;
                    g_h0t[dir][s&1][(u0+uu)*16 + b] = hn;
                }
            } else {
                if (s >= 1){
                    int t = s - 1;
                    float z[4];
                    #pragma unroll
                    for (int g=0; g<4; g++){
                        int x = g*8 + uu, par = x&1;
                        int cp1 = 16 + (x>>1), cp2 = 32 + (x>>1);
                        float a = b1[g*512 + u0 + uu];
                        #pragma unroll
                        for (int qq=0; qq<4; qq++)
                            a += zpf[(((qq*48 + cp1)*16) + b)*2 + par]
                               + zpf[(((qq*48 + cp2)*16) + b)*2 + par];
                        z[g] = a;
                    }
                    float cold = c1s[id];
                    float cn = sigf(z[1])*cold + sigf(z[0])*tanhfast(z[2]);
                    float hn = sigf(z[3])*tanhfast(cn);
                    int pos = dir ? (127 - t) : t;
                    if (seqs[b*TT + pos] == 0){
                        cn = cold; hn = ht1s[(u0+uu)*16 + b];
                    }
                    c1s[id] = cn;
                    g_h1t[dir][(s+1)&1][(u0+uu)*16 + b] = hn;
                    int r = dir ? (b*NS + (125 - t)) : (b*NS + t);
                    g_o[(size_t)r*OC + dir*UH + u0 + uu] = hn;
                }
            }
        }

        __threadfence();
        __syncthreads();
        if (tid == 0){
            unsigned v = atomicAdd(&g_cnt, 1u) + 1u;
            unsigned tgt = (unsigned)NBLK * (unsigned)(s+1);
            if (v == tgt) g_gen = (unsigned)(s+1);
            else while (g_gen < (unsigned)(s+1)) { }
        }
        __syncthreads();
    }
}

// ---------------- fp16 split/pack kernels ----------------
__global__ void k_splitA(){
    int i = blockIdx.x*blockDim.x + threadIdx.x;      // 2048*1024
    if (i >= 2048*1024) return;
    int r = i >> 10, k = i & 1023;
    float x = (r < OROWS) ? g_o[(size_t)r*OC + k] : 0.f;
    __half hi = __float2half_rn(x);
    float resid = x - __half2float(hi);
    A_h[(size_t)r*2048 + k]        = hi;
    A_h[(size_t)r*2048 + 1024 + k] = __float2half_rn(resid);
}

__global__ __launch_bounds__(256) void k_splitB(const float* __restrict__ Wp){
    __shared__ float tile[32][33];
    int n0 = blockIdx.x*32, k0 = blockIdx.y*32;
    int tx = threadIdx.x & 31, ty = threadIdx.x >> 5;   // ty 0..7
    #pragma unroll
    for (int i=0;i<4;i++){
        int k = k0 + ty + i*8;
        tile[ty+i*8][tx] = Wp[(size_t)k*V + n0 + tx];
    }
    __syncthreads();
    #pragma unroll
    for (int i=0;i<4;i++){
        int n = n0 + ty + i*8;
        float x = tile[tx][ty+i*8];
        B_h[(size_t)n*1024 + k0 + tx] = __float2half_rn(x);
    }
}

// ---------------- HMMA projection (mma.sync fp16, split-A) ----------------
// out[2016 x 32000] = (A_hi + A_lo) @ B^T + bp, effective K = 2048.
// BM=256, BN=128, BK=32, 512 threads (16 warps, warp tile 64x32).
#define PBM 256
#define PBN 128
#define PADK 40
#define PA_FL (2*PBM*PADK)            // halfs, double-buffered A
#define PB_FL (2*PBN*PADK)
#define PJ_SMEM ((PA_FL + PB_FL)*2)   // bytes = 61440

__global__ __launch_bounds__(512,1) void k_projhm(const float* __restrict__ bp,
                                                  float* __restrict__ Cout){
    extern __shared__ __half hsm[];
    __half* Asm = hsm;                 // [2][PBM][PADK]
    __half* Bsm = hsm + PA_FL;         // [2][PBN][PADK]

    const int tid  = threadIdx.x;
    const int wid  = tid >> 5;
    const int lane = tid & 31;
    const int m0 = blockIdx.y * PBM, n0 = blockIdx.x * PBN;
    const int wm = (wid & 3) * 64;     // warp row base in tile
    const int wn = (wid >> 2) * 32;    // warp col base in tile

    float acc[4][4][4];
    #pragma unroll
    for (int mf=0; mf<4; mf++)
        #pragma unroll
        for (int nf=0; nf<4; nf++)
            #pragma unroll
            for (int i=0; i<4; i++) acc[mf][nf][i] = 0.f;

    // ---- async tile loaders ----
    const int arow = tid >> 2, asg = tid & 3;          // A: 2 segs per thread
    const int brow = tid >> 2, bsg = tid & 3;          // B: threads 0..511 -> 512 segs
    uint32_t aDst0 = smem_u32(Asm) ;
    uint32_t bDst0 = smem_u32(Bsm);

    #define LOAD_CHUNK(buf, kA, kB) do { \
        uint32_t ab = aDst0 + (buf)*PBM*PADK*2; \
        cpa16(ab + (arow*PADK + asg*8)*2, \
              &A_h[(size_t)(m0 + arow)*2048 + (kA) + asg*8]); \
        cpa16(ab + ((arow+128)*PADK + asg*8)*2, \
              &A_h[(size_t)(m0 + arow + 128)*2048 + (kA) + asg*8]); \
        uint32_t bb2 = bDst0 + (buf)*PBN*PADK*2; \
        if (tid < 512) \
            cpa16(bb2 + (brow*PADK + bsg*8)*2, \
                  &B_h[(size_t)(n0 + brow)*1024 + (kB) + bsg*8]); \
        CPA_COMMIT(); \
    } while(0)

    LOAD_CHUNK(0, 0, 0);

    for (int kk = 0; kk < 64; kk++){
        int buf = kk & 1;
        if (kk < 63){
            int kn = kk + 1;
            int kA = (kn < 32) ? kn*32 : 1024 + (kn-32)*32;
            int kB = (kn & 31) * 32;
            LOAD_CHUNK(buf^1, kA, kB);
            CPA_WAIT1();
        } else {
            CPA_WAIT0();
        }
        __syncthreads();

        const uint32_t aBase = aDst0 + buf*PBM*PADK*2;
        const uint32_t bBase = bDst0 + buf*PBN*PADK*2;
        #pragma unroll
        for (int kf = 0; kf < 2; kf++){
            uint32_t a[4][4], b[4][2];
            int acol = kf*16 + ((lane & 16) ? 8 : 0);
            #pragma unroll
            for (int mf = 0; mf < 4; mf++){
                uint32_t addr = aBase + ((wm + mf*16 + (lane & 15))*PADK + acol)*2;
                LDSM_X4(a[mf][0], a[mf][1], a[mf][2], a[mf][3], addr);
            }
            int bcol = kf*16 + ((lane & 8) ? 8 : 0);
            #pragma unroll
            for (int nf = 0; nf < 4; nf++){
                uint32_t addr = bBase + ((wn + nf*8 + (lane & 7))*PADK + bcol)*2;
                LDSM_X2(b[nf][0], b[nf][1], addr);
            }
            #pragma unroll
            for (int mf = 0; mf < 4; mf++)
                #pragma unroll
                for (int nf = 0; nf < 4; nf++)
                    MMA16816(acc[mf][nf], a[mf], b[nf]);
        }
        __syncthreads();
    }

    // ---- epilogue: bias + store ----
    const int g = lane >> 2, tg = lane & 3;
    #pragma unroll
    for (int nf = 0; nf < 4; nf++){
        int n = n0 + wn + nf*8 + tg*2;
        float b0 = bp[n], b1 = bp[n+1];
        #pragma unroll
        for (int mf = 0; mf < 4; mf++){
            int m = m0 + wm + mf*16 + g;
            if (m < OROWS){
                float2 st; st.x = acc[mf][nf][0] + b0; st.y = acc[mf][nf][1] + b1;
                *(float2*)&Cout[(size_t)m*V + n] = st;
            }
            if (m + 8 < OROWS){
                float2 st; st.x = acc[mf][nf][2] + b0; st.y = acc[mf][nf][3] + b1;
                *(float2*)&Cout[(size_t)(m+8)*V + n] = st;
            }
        }
    }
}

// ---------------- launch ----------------
extern "C" void kernel_launch(void* const* d_in, const int* in_sizes, int n_in,
                              void* d_out, int out_size)
{
    const int*   seqs  = (const int*)  d_in[0];
    const float* embed = (const float*)d_in[1];
    const float* fW0   = (const float*)d_in[2];
    const float* fU0   = (const float*)d_in[3];
    const float* fb0   = (const float*)d_in[4];
    const float* fW1   = (const float*)d_in[5];
    const float* fU1   = (const float*)d_in[6];
    const float* fb1   = (const float*)d_in[7];
    const float* bW0   = (const float*)d_in[8];
    const float* bU0   = (const float*)d_in[9];
    const float* bb0   = (const float*)d_in[10];
    const float* bW1   = (const float*)d_in[11];
    const float* bU1   = (const float*)d_in[12];
    const float* bb1   = (const float*)d_in[13];
    const float* Wp    = (const float*)d_in[14];
    const float* bp    = (const float*)d_in[15];
    float* out = (float*)d_out;

    const int RSMEM = RSMEM_FL * 4;
    cudaFuncSetAttribute(k_recur, cudaFuncAttributeMaxDynamicSharedMemorySize, RSMEM);
    cudaFuncSetAttribute(k_projhm, cudaFuncAttributeMaxDynamicSharedMemorySize, PJ_SMEM);

    k_init<<<(2*2*UH*BB + 255)/256, 256>>>();
    k_embed<<<(BB*TT*(D/4) + 255)/256, 256>>>(seqs, embed);

    dim3 gx(8, 16, 2);
    k_xprep<<<gx, 256>>>(fW0, fb0, bW0, bb0);

    dim3 gb(V/32, OC/32, 1);                       // 1000 x 32
    k_splitB<<<gb, 256>>>(Wp);

    k_recur<<<NBLK, 256, RSMEM>>>(fU0, fW1, fU1, fb1, bU0, bW1, bU1, bb1, seqs);

    k_splitA<<<(2048*1024)/256, 256>>>();

    dim3 gp(V/PBN, 2048/PBM, 1);                   // 250 x 8 blocks
    k_projhm<<<gp, 512, PJ_SMEM>>>(bp, out);
}

// round 8
// speedup vs baseline: 4.4049x; 1.0711x over previous
#include <cuda_runtime.h>
#include <cuda_fp16.h>
#include <cstdint>
#include <math.h>

#define V   32000
#define D   256
#define UH  512
#define BB  16
#define TT  128
#define NS  126
#define G4  2048
#define OROWS (BB*NS)
#define OC  1024
#define NBLK 128
#define NSTEP 127

typedef unsigned long long ull;

// ---------------- device scratch ----------------
__device__ float g_emb[BB*TT*D];
__device__ float g_X[2][NS*BB*G4];
__device__ float g_h0t[2][2][UH*BB];
__device__ float g_h1t[2][2][UH*BB];
__device__ float g_o[(size_t)OROWS*OC];
__device__ unsigned g_cnt;
__device__ volatile unsigned g_gen;
// fp16 split operands for HMMA projection
__device__ __half A_h[(size_t)2048*2048];     // [m][ hi(1024) | resid(1024) ]
__device__ __half B_h[(size_t)32000*1024];    // [n][k]  (Wp^T, fp16)

// ---------------- f32x2 helpers ----------------
__device__ __forceinline__ ull pack2(float lo, float hi){
    ull r;
    asm("mov.b64 %0, {%1,%2};" : "=l"(r)
        : "r"(__float_as_uint(lo)), "r"(__float_as_uint(hi)));
    return r;
}
__device__ __forceinline__ void unpack2(ull v, float& lo, float& hi){
    unsigned a, b;
    asm("mov.b64 {%0,%1}, %2;" : "=r"(a), "=r"(b) : "l"(v));
    lo = __uint_as_float(a); hi = __uint_as_float(b);
}
__device__ __forceinline__ ull ffma2(ull a, ull b, ull c){
    ull r;
    asm("fma.rn.f32x2 %0, %1, %2, %3;" : "=l"(r) : "l"(a), "l"(b), "l"(c));
    return r;
}
__device__ __forceinline__ float sigf(float x){ return 1.f/(1.f + __expf(-x)); }
__device__ __forceinline__ float tanhfast(float x){ return 2.f/(1.f + __expf(-2.f*x)) - 1.f; }

// ---------------- arch-neutral PTX helpers ----------------
__device__ __forceinline__ uint32_t smem_u32(const void* p){
    uint32_t a;
    asm("{ .reg .u64 t; cvta.to.shared.u64 t, %1; cvt.u32.u64 %0, t; }" : "=r"(a) : "l"(p));
    return a;
}
__device__ __forceinline__ void cpa16(uint32_t s, const void* g){
    asm volatile("cp.async.cg.shared.global [%0], [%1], 16;" :: "r"(s), "l"(g) : "memory");
}
#define CPA_COMMIT() asm volatile("cp.async.commit_group;" ::: "memory")
#define CPA_WAIT1()  asm volatile("cp.async.wait_group 1;" ::: "memory")
#define CPA_WAIT0()  asm volatile("cp.async.wait_group 0;" ::: "memory")

#define LDSM_X4(r0,r1,r2,r3,addr) \
    asm volatile("ldmatrix.sync.aligned.m8n8.x4.shared.b16 {%0,%1,%2,%3}, [%4];" \
        : "=r"(r0), "=r"(r1), "=r"(r2), "=r"(r3) : "r"(addr))
#define LDSM_X2(r0,r1,addr) \
    asm volatile("ldmatrix.sync.aligned.m8n8.x2.shared.b16 {%0,%1}, [%2];" \
        : "=r"(r0), "=r"(r1) : "r"(addr))
#define MMA16816(c,a,b) \
    asm volatile("mma.sync.aligned.m16n8k16.row.col.f32.f16.f16.f32 " \
        "{%0,%1,%2,%3}, {%4,%5,%6,%7}, {%8,%9}, {%0,%1,%2,%3};" \
        : "+f"((c)[0]), "+f"((c)[1]), "+f"((c)[2]), "+f"((c)[3]) \
        : "r"((a)[0]), "r"((a)[1]), "r"((a)[2]), "r"((a)[3]), \
          "r"((b)[0]), "r"((b)[1]))

// ---------------- init (every replay) ----------------
__global__ void k_init(){
    int i = blockIdx.x*blockDim.x + threadIdx.x;
    int n = 2*2*UH*BB;
    if (i < n){
        ((float*)g_h0t)[i] = 0.f;
        ((float*)g_h1t)[i] = 0.f;
    }
    if (i == 0){ g_cnt = 0u; g_gen = 0u; }
}

// ---------------- embedding gather ----------------
__global__ void k_embed(const int* __restrict__ seqs, const float* __restrict__ embed){
    int i = blockIdx.x*blockDim.x + threadIdx.x;
    if (i >= BB*TT*(D/4)) return;
    int bt = i / (D/4);
    int d4 = i % (D/4);
    int tok = seqs[bt];
    float4 v = *(const float4*)&embed[(size_t)tok*D + d4*4];
    *(float4*)&g_emb[(size_t)bt*D + d4*4] = v;
}

// ---------------- X precompute GEMM (fp32 FFMA2) ----------------
__global__ __launch_bounds__(256) void k_xprep(const float* __restrict__ fW0,
                                               const float* __restrict__ fb0,
                                               const float* __restrict__ bW0,
                                               const float* __restrict__ bb0){
    const int dir = blockIdx.z;
    const float* W    = dir ? bW0 : fW0;
    const float* bias = dir ? bb0 : fb0;
    float* out = g_X[dir];
    const int m0 = blockIdx.y*128, n0 = blockIdx.x*256;
    __shared__ float As[16][128];
    __shared__ float Bs[16][256];
    const int tid = threadIdx.x;
    const int tx = tid & 15, ty = tid >> 4;

    ull acc[8][8];
    #pragma unroll
    for (int i=0;i<8;i++)
        #pragma unroll
        for (int q=0;q<8;q++) acc[i][q] = 0ull;

    for (int kt=0; kt<16; kt++){
        #pragma unroll
        for (int i=0;i<2;i++){
            int lin = tid + i*256;
            int row = lin>>2, c4 = lin&3;
            int r = m0 + row;
            float4 v = make_float4(0.f,0.f,0.f,0.f);
            if (r < OROWS){
                int t = r>>4, b = r&15;
                int txi = dir ? (127 - t) : t;
                v = *(const float4*)&g_emb[((b<<7)+txi)*D + kt*16 + c4*4];
            }
            As[c4*4+0][row]=v.x; As[c4*4+1][row]=v.y;
            As[c4*4+2][row]=v.z; As[c4*4+3][row]=v.w;
        }
        #pragma unroll
        for (int i=0;i<4;i++){
            int lin = tid + i*256;
            int kr = lin>>6, c4 = lin&63;
            *(float4*)&Bs[kr][c4*4] =
                *(const float4*)&W[(size_t)(kt*16+kr)*G4 + n0 + c4*4];
        }
        __syncthreads();
        #pragma unroll
        for (int k=0;k<16;k++){
            float a0[8];
            *(float4*)&a0[0] = *(float4*)&As[k][ty*8];
            *(float4*)&a0[4] = *(float4*)&As[k][ty*8+4];
            ull av[8];
            #pragma unroll
            for (int i=0;i<8;i++) av[i] = pack2(a0[i], a0[i]);
            ull bv[8];
            #pragma unroll
            for (int q=0;q<4;q++){
                ulonglong2 p = *(const ulonglong2*)&Bs[k][tx*16 + q*4];
                bv[2*q] = p.x; bv[2*q+1] = p.y;
            }
            #pragma unroll
            for (int i=0;i<8;i++)
                #pragma unroll
                for (int q=0;q<8;q++)
                    acc[i][q] = ffma2(av[i], bv[q], acc[i][q]);
        }
        __syncthreads();
    }
    #pragma unroll
    for (int i=0;i<8;i++){
        int r = m0 + ty*8 + i;
        if (r >= OROWS) continue;
        float* crow = out + (size_t)r*G4 + n0 + tx*16;
        #pragma unroll
        for (int q=0;q<8;q++){
            float lo,hi; unpack2(acc[i][q], lo, hi);
            int col = n0 + tx*16 + 2*q;
            float2 st; st.x = lo + bias[col]; st.y = hi + bias[col+1];
            *(float2*)&crow[2*q] = st;
        }
    }
}

// ---------------- persistent recurrence (R7 retile, h-index FIXED) ----------------
#define WSQ_FL   (8*1025*4)
#define HT_FL    (UH*BB)
#define ZP_FL    (8*32*8*2)
#define RSMEM_FL (WSQ_FL + 2*HT_FL + 2*ZP_FL + 256)

__global__ __launch_bounds__(256,1) void k_recur(
    const float* __restrict__ fU0, const float* __restrict__ fW1,
    const float* __restrict__ fU1, const float* __restrict__ fb1,
    const float* __restrict__ bU0, const float* __restrict__ bW1,
    const float* __restrict__ bU1, const float* __restrict__ bb1,
    const int*   __restrict__ seqs)
{
    extern __shared__ float sm[];
    float* wsQ  = sm;                          // [cq][k] float4 stride 1025
    float* ht0s = sm + WSQ_FL;                 // [k][16]
    float* ht1s = ht0s + HT_FL;
    float* zpAf = ht1s + HT_FL;                // [w][32][8][2]
    float* zpBf = zpAf + ZP_FL;
    float* c0s  = zpBf + ZP_FL;                // [128]
    float* c1s  = c0s + 128;
    ull* zpAu = (ull*)zpAf;
    ull* zpBu = (ull*)zpBf;

    const int tid  = threadIdx.x;
    const int wid  = tid >> 5;
    const int lane = tid & 31;
    const int blk  = blockIdx.x;
    const int dir  = blk >> 6;
    const int u0   = (blk & 63) * 8;

    const float* U0 = dir ? bU0 : fU0;
    const float* W1 = dir ? bW1 : fW1;
    const float* U1 = dir ? bU1 : fU1;
    const float* b1 = dir ? bb1 : fb1;
    const float* Xp = g_X[dir];

    // ---- preload U0|W1 into wsQuad (once) ----
    for (int idx = tid; idx < 8*1024; idx += 256){
        int cq = idx >> 10, k = idx & 1023;
        int kk = k & 511;
        const float* Wsrc = (k < 512) ? U0 : W1;
        int jb = (cq>>1)*512 + u0 + (cq&1)*4;
        float4 v = *(const float4*)&Wsrc[(size_t)kk*G4 + jb];
        *(float4*)&wsQ[((size_t)cq*1025 + k)*4] = v;
    }
    if (tid < 128){ c0s[tid] = 0.f; c1s[tid] = 0.f; }
    __syncthreads();

    const int cq = lane & 7;          // col quad: cols 4cq..4cq+3
    const int bq = lane >> 3;         // batch quad: batches 4bq..4bq+3
    const int kbA = wid * 128;        // phase A weight k-range (0..1023)
    const int kA0 = kbA & 511;        // phase A h-index base (BOTH halves read ht0s!)
    const int kbB = wid * 64;         // phase B k-range (0..511)
    const float* wA = wsQ + ((size_t)cq*1025 + kbA)*4;
    const float* UgB = U1 + (size_t)((cq>>1)*512 + u0 + (cq&1)*4);

    for (int s = 0; s < NSTEP; s++){
        // ---- stage h0[s-1], h1[s-2] ----
        {
            const float4* s0 = (const float4*)g_h0t[dir][(s+1)&1];
            const float4* s1 = (const float4*)g_h1t[dir][s&1];
            float4* d0 = (float4*)ht0s;
            float4* d1 = (float4*)ht1s;
            #pragma unroll
            for (int i=0;i<8;i++){ int ix = tid + i*256; d0[ix] = __ldcg(s0+ix); }
            #pragma unroll
            for (int i=0;i<8;i++){ int ix = tid + i*256; d1[ix] = __ldcg(s1+ix); }
        }

        // phase-B prologue prefetch — overlaps staging + phase A
        float4 wb0[8], wb1[8];
        #pragma unroll
        for (int i=0;i<8;i++)
            wb0[i] = __ldcg((const float4*)(UgB + (size_t)(kbB+i)*G4));

        __syncthreads();

        // ---- phase A: U0|W1 (smem weights), h0 (smem) ----
        ull accA[4][2];
        #pragma unroll
        for (int c=0;c<4;c++){ accA[c][0]=0ull; accA[c][1]=0ull; }
        {
            const float* hp = ht0s + (size_t)kA0*16 + bq*4;
            #pragma unroll 8
            for (int k=0;k<128;k++){
                float4 wv = *(const float4*)(wA + (size_t)k*4);
                ulonglong2 h2 = *(const ulonglong2*)(hp + (size_t)k*16);
                ull w0 = pack2(wv.x,wv.x), w1 = pack2(wv.y,wv.y);
                ull w2 = pack2(wv.z,wv.z), w3 = pack2(wv.w,wv.w);
                accA[0][0]=ffma2(w0,h2.x,accA[0][0]); accA[0][1]=ffma2(w0,h2.y,accA[0][1]);
                accA[1][0]=ffma2(w1,h2.x,accA[1][0]); accA[1][1]=ffma2(w1,h2.y,accA[1][1]);
                accA[2][0]=ffma2(w2,h2.x,accA[2][0]); accA[2][1]=ffma2(w2,h2.y,accA[2][1]);
                accA[3][0]=ffma2(w3,h2.x,accA[3][0]); accA[3][1]=ffma2(w3,h2.y,accA[3][1]);
            }
        }

        // ---- phase B: U1 (gmem stream), h1 (smem) ----
        ull accB[4][2];
        #pragma unroll
        for (int c=0;c<4;c++){ accB[c][0]=0ull; accB[c][1]=0ull; }
        #pragma unroll
        for (int i=0;i<8;i++)
            wb1[i] = __ldcg((const float4*)(UgB + (size_t)(kbB+8+i)*G4));
        {
            const float* hp = ht1s + bq*4;
            #pragma unroll
            for (int g=0; g<8; g++){
                #pragma unroll
                for (int i=0;i<8;i++){
                    int k = kbB + g*8 + i;
                    float4 wv = (g&1) ? wb1[i] : wb0[i];
                    ulonglong2 h2 = *(const ulonglong2*)(hp + (size_t)k*16);
                    ull w0 = pack2(wv.x,wv.x), w1 = pack2(wv.y,wv.y);
                    ull w2 = pack2(wv.z,wv.z), w3 = pack2(wv.w,wv.w);
                    accB[0][0]=ffma2(w0,h2.x,accB[0][0]); accB[0][1]=ffma2(w0,h2.y,accB[0][1]);
                    accB[1][0]=ffma2(w1,h2.x,accB[1][0]); accB[1][1]=ffma2(w1,h2.y,accB[1][1]);
                    accB[2][0]=ffma2(w2,h2.x,accB[2][0]); accB[2][1]=ffma2(w2,h2.y,accB[2][1]);
                    accB[3][0]=ffma2(w3,h2.x,accB[3][0]); accB[3][1]=ffma2(w3,h2.y,accB[3][1]);
                    if (g < 6){
                        if (g&1) wb1[i] = __ldcg((const float4*)(UgB + (size_t)(k+16)*G4));
                        else     wb0[i] = __ldcg((const float4*)(UgB + (size_t)(k+16)*G4));
                    }
                }
            }
        }

        // ---- write partials ----
        #pragma unroll
        for (int c=0;c<4;c++){
            int col = cq*4 + c;
            #pragma unroll
            for (int p=0;p<2;p++){
                int bp = bq*2 + p;
                zpAu[((size_t)wid*32 + col)*8 + bp] = accA[c][p];
                zpBu[((size_t)wid*32 + col)*8 + bp] = accB[c][p];
            }
        }
        __syncthreads();

        // ---- activation / state update ----
        {
            int layer = tid >> 7, id = tid & 127;
            int uu = id >> 4, b = id & 15;
            int bp = b >> 1, par = b & 1;
            if (layer == 0){
                if (s < NS){
                    int t = s;
                    float z[4];
                    #pragma unroll
                    for (int g=0; g<4; g++){
                        int col = g*8 + uu;
                        float a = Xp[(size_t)((t<<4)+b)*G4 + g*512 + u0 + uu];
                        #pragma unroll
                        for (int w=0; w<4; w++)
                            a += zpAf[(((size_t)w*32 + col)*8 + bp)*2 + par];
                        z[g] = a;
                    }
                    float cold = c0s[id];
                    float cn = sigf(z[1])*cold + sigf(z[0])*tanhfast(z[2]);
                    float hn = sigf(z[3])*tanhfast(cn);
                    int pos = dir ? (127 - t) : t;
                    if (seqs[b*TT + pos] == 0){
                        cn = cold; hn = ht0s[(u0+uu)*16 + b];
                    }
                    c0s[id] = cn;
                    g_h0t[dir][s&1][(u0+uu)*16 + b] = hn;
                }
            } else {
                if (s >= 1){
                    int t = s - 1;
                    float z[4];
                    #pragma unroll
                    for (int g=0; g<4; g++){
                        int col = g*8 + uu;
                        float a = b1[g*512 + u0 + uu];
                        #pragma unroll
                        for (int w=4; w<8; w++)
                            a += zpAf[(((size_t)w*32 + col)*8 + bp)*2 + par];
                        #pragma unroll
                        for (int w=0; w<8; w++)
                            a += zpBf[(((size_t)w*32 + col)*8 + bp)*2 + par];
                        z[g] = a;
                    }
                    float cold = c1s[id];
                    float cn = sigf(z[1])*cold + sigf(z[0])*tanhfast(z[2]);
                    float hn = sigf(z[3])*tanhfast(cn);
                    int pos = dir ? (127 - t) : t;
                    if (seqs[b*TT + pos] == 0){
                        cn = cold; hn = ht1s[(u0+uu)*16 + b];
                    }
                    c1s[id] = cn;
                    g_h1t[dir][(s+1)&1][(u0+uu)*16 + b] = hn;
                    int r = dir ? (b*NS + (125 - t)) : (b*NS + t);
                    g_o[(size_t)r*OC + dir*UH + u0 + uu] = hn;
                }
            }
        }

        // ---- grid barrier ----
        __threadfence();
        __syncthreads();
        if (tid == 0){
            unsigned v = atomicAdd(&g_cnt, 1u) + 1u;
            unsigned tgt = (unsigned)NBLK * (unsigned)(s+1);
            if (v == tgt) g_gen = (unsigned)(s+1);
            else while (g_gen < (unsigned)(s+1)) { }
        }
        __syncthreads();
    }
}

// ---------------- fp16 split/pack kernels ----------------
__global__ void k_splitA(){
    int i = blockIdx.x*blockDim.x + threadIdx.x;
    if (i >= 2048*1024) return;
    int r = i >> 10, k = i & 1023;
    float x = (r < OROWS) ? g_o[(size_t)r*OC + k] : 0.f;
    __half hi = __float2half_rn(x);
    float resid = x - __half2float(hi);
    A_h[(size_t)r*2048 + k]        = hi;
    A_h[(size_t)r*2048 + 1024 + k] = __float2half_rn(resid);
}

__global__ __launch_bounds__(256) void k_splitB(const float* __restrict__ Wp){
    __shared__ float tile[32][33];
    int n0 = blockIdx.x*32, k0 = blockIdx.y*32;
    int tx = threadIdx.x & 31, ty = threadIdx.x >> 5;
    #pragma unroll
    for (int i=0;i<4;i++){
        int k = k0 + ty + i*8;
        tile[ty+i*8][tx] = Wp[(size_t)k*V + n0 + tx];
    }
    __syncthreads();
    #pragma unroll
    for (int i=0;i<4;i++){
        int n = n0 + ty + i*8;
        float x = tile[tx][ty+i*8];
        B_h[(size_t)n*1024 + k0 + tx] = __float2half_rn(x);
    }
}

// ---------------- HMMA projection ----------------
#define PBM 256
#define PBN 128
#define PADK 40
#define PA_FL (2*PBM*PADK)
#define PB_FL (2*PBN*PADK)
#define PJ_SMEM ((PA_FL + PB_FL)*2)

__global__ __launch_bounds__(512,1) void k_projhm(const float* __restrict__ bp,
                                                  float* __restrict__ Cout){
    extern __shared__ __half hsm[];
    __half* Asm = hsm;
    __half* Bsm = hsm + PA_FL;

    const int tid  = threadIdx.x;
    const int wid  = tid >> 5;
    const int lane = tid & 31;
    const int m0 = blockIdx.y * PBM, n0 = blockIdx.x * PBN;
    const int wm = (wid & 3) * 64;
    const int wn = (wid >> 2) * 32;

    float acc[4][4][4];
    #pragma unroll
    for (int mf=0; mf<4; mf++)
        #pragma unroll
        for (int nf=0; nf<4; nf++)
            #pragma unroll
            for (int i=0; i<4; i++) acc[mf][nf][i] = 0.f;

    const int arow = tid >> 2, asg = tid & 3;
    const int brow = tid >> 2, bsg = tid & 3;
    uint32_t aDst0 = smem_u32(Asm);
    uint32_t bDst0 = smem_u32(Bsm);

    #define LOAD_CHUNK(buf, kA, kB) do { \
        uint32_t ab = aDst0 + (buf)*PBM*PADK*2; \
        cpa16(ab + (arow*PADK + asg*8)*2, \
              &A_h[(size_t)(m0 + arow)*2048 + (kA) + asg*8]); \
        cpa16(ab + ((arow+128)*PADK + asg*8)*2, \
              &A_h[(size_t)(m0 + arow + 128)*2048 + (kA) + asg*8]); \
        uint32_t bb2 = bDst0 + (buf)*PBN*PADK*2; \
        if (tid < 512) \
            cpa16(bb2 + (brow*PADK + bsg*8)*2, \
                  &B_h[(size_t)(n0 + brow)*1024 + (kB) + bsg*8]); \
        CPA_COMMIT(); \
    } while(0)

    LOAD_CHUNK(0, 0, 0);

    for (int kk = 0; kk < 64; kk++){
        int buf = kk & 1;
        if (kk < 63){
            int kn = kk + 1;
            int kA = (kn < 32) ? kn*32 : 1024 + (kn-32)*32;
            int kB = (kn & 31) * 32;
            LOAD_CHUNK(buf^1, kA, kB);
            CPA_WAIT1();
        } else {
            CPA_WAIT0();
        }
        __syncthreads();

        const uint32_t aBase = aDst0 + buf*PBM*PADK*2;
        const uint32_t bBase = bDst0 + buf*PBN*PADK*2;
        #pragma unroll
        for (int kf = 0; kf < 2; kf++){
            uint32_t a[4][4], b[4][2];
            int acol = kf*16 + ((lane & 16) ? 8 : 0);
            #pragma unroll
            for (int mf = 0; mf < 4; mf++){
                uint32_t addr = aBase + ((wm + mf*16 + (lane & 15))*PADK + acol)*2;
                LDSM_X4(a[mf][0], a[mf][1], a[mf][2], a[mf][3], addr);
            }
            int bcol = kf*16 + ((lane & 8) ? 8 : 0);
            #pragma unroll
            for (int nf = 0; nf < 4; nf++){
                uint32_t addr = bBase + ((wn + nf*8 + (lane & 7))*PADK + bcol)*2;
                LDSM_X2(b[nf][0], b[nf][1], addr);
            }
            #pragma unroll
            for (int mf = 0; mf < 4; mf++)
                #pragma unroll
                for (int nf = 0; nf < 4; nf++)
                    MMA16816(acc[mf][nf], a[mf], b[nf]);
        }
        __syncthreads();
    }

    const int g = lane >> 2, tg = lane & 3;
    #pragma unroll
    for (int nf = 0; nf < 4; nf++){
        int n = n0 + wn + nf*8 + tg*2;
        float b0 = bp[n], b1 = bp[n+1];
        #pragma unroll
        for (int mf = 0; mf < 4; mf++){
            int m = m0 + wm + mf*16 + g;
            if (m < OROWS){
                float2 st; st.x = acc[mf][nf][0] + b0; st.y = acc[mf][nf][1] + b1;
                *(float2*)&Cout[(size_t)m*V + n] = st;
            }
            if (m + 8 < OROWS){
                float2 st; st.x = acc[mf][nf][2] + b0; st.y = acc[mf][nf][3] + b1;
                *(float2*)&Cout[(size_t)(m+8)*V + n] = st;
            }
        }
    }
}

// ---------------- launch ----------------
extern "C" void kernel_launch(void* const* d_in, const int* in_sizes, int n_in,
                              void* d_out, int out_size)
{
    const int*   seqs  = (const int*)  d_in[0];
    const float* embed = (const float*)d_in[1];
    const float* fW0   = (const float*)d_in[2];
    const float* fU0   = (const float*)d_in[3];
    const float* fb0   = (const float*)d_in[4];
    const float* fW1   = (const float*)d_in[5];
    const float* fU1   = (const float*)d_in[6];
    const float* fb1   = (const float*)d_in[7];
    const float* bW0   = (const float*)d_in[8];
    const float* bU0   = (const float*)d_in[9];
    const float* bb0   = (const float*)d_in[10];
    const float* bW1   = (const float*)d_in[11];
    const float* bU1   = (const float*)d_in[12];
    const float* bb1   = (const float*)d_in[13];
    const float* Wp    = (const float*)d_in[14];
    const float* bp    = (const float*)d_in[15];
    float* out = (float*)d_out;

    const int RSMEM = RSMEM_FL * 4;
    cudaFuncSetAttribute(k_recur, cudaFuncAttributeMaxDynamicSharedMemorySize, RSMEM);
    cudaFuncSetAttribute(k_projhm, cudaFuncAttributeMaxDynamicSharedMemorySize, PJ_SMEM);

    k_init<<<(2*2*UH*BB + 255)/256, 256>>>();
    k_embed<<<(BB*TT*(D/4) + 255)/256, 256>>>(seqs, embed);

    dim3 gx(8, 16, 2);
    k_xprep<<<gx, 256>>>(fW0, fb0, bW0, bb0);

    dim3 gb(V/32, OC/32, 1);
    k_splitB<<<gb, 256>>>(Wp);

    k_recur<<<NBLK, 256, RSMEM>>>(fU0, fW1, fU1, fb1, bU0, bW1, bU1, bb1, seqs);

    k_splitA<<<(2048*1024)/256, 256>>>();

    dim3 gp(V/PBN, 2048/PBM, 1);
    k_projhm<<<gp, 512, PJ_SMEM>>>(bp, out);
}

// round 9
// speedup vs baseline: 5.2884x; 1.2006x over previous
#include <cuda_runtime.h>
#include <cuda_fp16.h>
#include <cstdint>
#include <math.h>

#define V   32000
#define D   256
#define UH  512
#define BB  16
#define TT  128
#define NS  126
#define G4  2048
#define OROWS (BB*NS)
#define OC  1024
#define NBLK 128
#define NSTEP 127

typedef unsigned long long ull;

// ---------------- device scratch ----------------
__device__ float g_emb[BB*TT*D];
__device__ float g_X[2][NS*BB*G4];
__device__ float g_h0t[2][2][UH*BB];
__device__ float g_h1t[2][2][UH*BB];
__device__ unsigned g_cnt;
__device__ volatile unsigned g_gen;
// fp16 operands for HMMA projection (A_h rows >= OROWS stay zero-initialized)
__device__ __half A_h[(size_t)2048*1024];     // [m][k]  (concat h, fp16)
__device__ __half B_h[(size_t)32000*1024];    // [n][k]  (Wp^T, fp16)

// ---------------- f32x2 helpers ----------------
__device__ __forceinline__ ull pack2(float lo, float hi){
    ull r;
    asm("mov.b64 %0, {%1,%2};" : "=l"(r)
        : "r"(__float_as_uint(lo)), "r"(__float_as_uint(hi)));
    return r;
}
__device__ __forceinline__ void unpack2(ull v, float& lo, float& hi){
    unsigned a, b;
    asm("mov.b64 {%0,%1}, %2;" : "=r"(a), "=r"(b) : "l"(v));
    lo = __uint_as_float(a); hi = __uint_as_float(b);
}
__device__ __forceinline__ ull ffma2(ull a, ull b, ull c){
    ull r;
    asm("fma.rn.f32x2 %0, %1, %2, %3;" : "=l"(r) : "l"(a), "l"(b), "l"(c));
    return r;
}
__device__ __forceinline__ float sigf(float x){ return 1.f/(1.f + __expf(-x)); }
__device__ __forceinline__ float tanhfast(float x){ return 2.f/(1.f + __expf(-2.f*x)) - 1.f; }

// ---------------- arch-neutral PTX helpers ----------------
__device__ __forceinline__ uint32_t smem_u32(const void* p){
    uint32_t a;
    asm("{ .reg .u64 t; cvta.to.shared.u64 t, %1; cvt.u32.u64 %0, t; }" : "=r"(a) : "l"(p));
    return a;
}
__device__ __forceinline__ void cpa16(uint32_t s, const void* g){
    asm volatile("cp.async.cg.shared.global [%0], [%1], 16;" :: "r"(s), "l"(g) : "memory");
}
#define CPA_COMMIT() asm volatile("cp.async.commit_group;" ::: "memory")
#define CPA_WAIT1()  asm volatile("cp.async.wait_group 1;" ::: "memory")
#define CPA_WAIT0()  asm volatile("cp.async.wait_group 0;" ::: "memory")

#define LDSM_X4(r0,r1,r2,r3,addr) \
    asm volatile("ldmatrix.sync.aligned.m8n8.x4.shared.b16 {%0,%1,%2,%3}, [%4];" \
        : "=r"(r0), "=r"(r1), "=r"(r2), "=r"(r3) : "r"(addr))
#define LDSM_X2(r0,r1,addr) \
    asm volatile("ldmatrix.sync.aligned.m8n8.x2.shared.b16 {%0,%1}, [%2];" \
        : "=r"(r0), "=r"(r1) : "r"(addr))
#define MMA16816(c,a,b) \
    asm volatile("mma.sync.aligned.m16n8k16.row.col.f32.f16.f16.f32 " \
        "{%0,%1,%2,%3}, {%4,%5,%6,%7}, {%8,%9}, {%0,%1,%2,%3};" \
        : "+f"((c)[0]), "+f"((c)[1]), "+f"((c)[2]), "+f"((c)[3]) \
        : "r"((a)[0]), "r"((a)[1]), "r"((a)[2]), "r"((a)[3]), \
          "r"((b)[0]), "r"((b)[1]))

// ---------------- init (every replay) ----------------
__global__ void k_init(){
    int i = blockIdx.x*blockDim.x + threadIdx.x;
    int n = 2*2*UH*BB;
    if (i < n){
        ((float*)g_h0t)[i] = 0.f;
        ((float*)g_h1t)[i] = 0.f;
    }
    if (i == 0){ g_cnt = 0u; g_gen = 0u; }
}

// ---------------- embedding gather ----------------
__global__ void k_embed(const int* __restrict__ seqs, const float* __restrict__ embed){
    int i = blockIdx.x*blockDim.x + threadIdx.x;
    if (i >= BB*TT*(D/4)) return;
    int bt = i / (D/4);
    int d4 = i % (D/4);
    int tok = seqs[bt];
    float4 v = *(const float4*)&embed[(size_t)tok*D + d4*4];
    *(float4*)&g_emb[(size_t)bt*D + d4*4] = v;
}

// ---------------- X precompute GEMM (fp32 FFMA2) ----------------
__global__ __launch_bounds__(256) void k_xprep(const float* __restrict__ fW0,
                                               const float* __restrict__ fb0,
                                               const float* __restrict__ bW0,
                                               const float* __restrict__ bb0){
    const int dir = blockIdx.z;
    const float* W    = dir ? bW0 : fW0;
    const float* bias = dir ? bb0 : fb0;
    float* out = g_X[dir];
    const int m0 = blockIdx.y*128, n0 = blockIdx.x*256;
    __shared__ float As[16][128];
    __shared__ float Bs[16][256];
    const int tid = threadIdx.x;
    const int tx = tid & 15, ty = tid >> 4;

    ull acc[8][8];
    #pragma unroll
    for (int i=0;i<8;i++)
        #pragma unroll
        for (int q=0;q<8;q++) acc[i][q] = 0ull;

    for (int kt=0; kt<16; kt++){
        #pragma unroll
        for (int i=0;i<2;i++){
            int lin = tid + i*256;
            int row = lin>>2, c4 = lin&3;
            int r = m0 + row;
            float4 v = make_float4(0.f,0.f,0.f,0.f);
            if (r < OROWS){
                int t = r>>4, b = r&15;
                int txi = dir ? (127 - t) : t;
                v = *(const float4*)&g_emb[((b<<7)+txi)*D + kt*16 + c4*4];
            }
            As[c4*4+0][row]=v.x; As[c4*4+1][row]=v.y;
            As[c4*4+2][row]=v.z; As[c4*4+3][row]=v.w;
        }
        #pragma unroll
        for (int i=0;i<4;i++){
            int lin = tid + i*256;
            int kr = lin>>6, c4 = lin&63;
            *(float4*)&Bs[kr][c4*4] =
                *(const float4*)&W[(size_t)(kt*16+kr)*G4 + n0 + c4*4];
        }
        __syncthreads();
        #pragma unroll
        for (int k=0;k<16;k++){
            float a0[8];
            *(float4*)&a0[0] = *(float4*)&As[k][ty*8];
            *(float4*)&a0[4] = *(float4*)&As[k][ty*8+4];
            ull av[8];
            #pragma unroll
            for (int i=0;i<8;i++) av[i] = pack2(a0[i], a0[i]);
            ull bv[8];
            #pragma unroll
            for (int q=0;q<4;q++){
                ulonglong2 p = *(const ulonglong2*)&Bs[k][tx*16 + q*4];
                bv[2*q] = p.x; bv[2*q+1] = p.y;
            }
            #pragma unroll
            for (int i=0;i<8;i++)
                #pragma unroll
                for (int q=0;q<8;q++)
                    acc[i][q] = ffma2(av[i], bv[q], acc[i][q]);
        }
        __syncthreads();
    }
    #pragma unroll
    for (int i=0;i<8;i++){
        int r = m0 + ty*8 + i;
        if (r >= OROWS) continue;
        float* crow = out + (size_t)r*G4 + n0 + tx*16;
        #pragma unroll
        for (int q=0;q<8;q++){
            float lo,hi; unpack2(acc[i][q], lo, hi);
            int col = n0 + tx*16 + 2*q;
            float2 st; st.x = lo + bias[col]; st.y = hi + bias[col+1];
            *(float2*)&crow[2*q] = st;
        }
    }
}

// ---------------- persistent recurrence ----------------
#define WSQ_FL   (8*1025*4)
#define HT_FL    (UH*BB)
#define ZP_FL    (8*32*8*2)
#define RSMEM_FL (WSQ_FL + 2*HT_FL + 2*ZP_FL + 256)

__global__ __launch_bounds__(256,1) void k_recur(
    const float* __restrict__ fU0, const float* __restrict__ fW1,
    const float* __restrict__ fU1, const float* __restrict__ fb1,
    const float* __restrict__ bU0, const float* __restrict__ bW1,
    const float* __restrict__ bU1, const float* __restrict__ bb1,
    const int*   __restrict__ seqs)
{
    extern __shared__ float sm[];
    float* wsQ  = sm;                          // [cq][k] float4 stride 1025
    float* ht0s = sm + WSQ_FL;                 // [k][16]
    float* ht1s = ht0s + HT_FL;
    float* zpAf = ht1s + HT_FL;                // [w][32][8][2]
    float* zpBf = zpAf + ZP_FL;
    float* c0s  = zpBf + ZP_FL;                // [128]
    float* c1s  = c0s + 128;
    ull* zpAu = (ull*)zpAf;
    ull* zpBu = (ull*)zpBf;

    const int tid  = threadIdx.x;
    const int wid  = tid >> 5;
    const int lane = tid & 31;
    const int blk  = blockIdx.x;
    const int dir  = blk >> 6;
    const int u0   = (blk & 63) * 8;

    const float* U0 = dir ? bU0 : fU0;
    const float* W1 = dir ? bW1 : fW1;
    const float* U1 = dir ? bU1 : fU1;
    const float* b1 = dir ? bb1 : fb1;
    const float* Xp = g_X[dir];

    // ---- preload U0|W1 into wsQuad (once) ----
    for (int idx = tid; idx < 8*1024; idx += 256){
        int cq = idx >> 10, k = idx & 1023;
        int kk = k & 511;
        const float* Wsrc = (k < 512) ? U0 : W1;
        int jb = (cq>>1)*512 + u0 + (cq&1)*4;
        float4 v = *(const float4*)&Wsrc[(size_t)kk*G4 + jb];
        *(float4*)&wsQ[((size_t)cq*1025 + k)*4] = v;
    }
    if (tid < 128){ c0s[tid] = 0.f; c1s[tid] = 0.f; }
    __syncthreads();

    const int cq = lane & 7;          // col quad: cols 4cq..4cq+3
    const int bq = lane >> 3;         // batch quad: batches 4bq..4bq+3
    const int kbA = wid * 128;        // phase A weight k-range (0..1023)
    const int kA0 = kbA & 511;        // phase A h-index base (both halves read ht0s)
    const int kbB = wid * 64;         // phase B k-range (0..511)
    const float* wA = wsQ + ((size_t)cq*1025 + kbA)*4;
    const float* UgB = U1 + (size_t)((cq>>1)*512 + u0 + (cq&1)*4);

    for (int s = 0; s < NSTEP; s++){
        // ---- stage h0[s-1], h1[s-2] ----
        {
            const float4* s0 = (const float4*)g_h0t[dir][(s+1)&1];
            const float4* s1 = (const float4*)g_h1t[dir][s&1];
            float4* d0 = (float4*)ht0s;
            float4* d1 = (float4*)ht1s;
            #pragma unroll
            for (int i=0;i<8;i++){ int ix = tid + i*256; d0[ix] = __ldcg(s0+ix); }
            #pragma unroll
            for (int i=0;i<8;i++){ int ix = tid + i*256; d1[ix] = __ldcg(s1+ix); }
        }

        // phase-B prologue prefetch — overlaps staging + phase A
        float4 wb0[8], wb1[8];
        #pragma unroll
        for (int i=0;i<8;i++)
            wb0[i] = __ldcg((const float4*)(UgB + (size_t)(kbB+i)*G4));

        __syncthreads();

        // ---- phase A: U0|W1 (smem weights), h0 (smem) ----
        ull accA[4][2];
        #pragma unroll
        for (int c=0;c<4;c++){ accA[c][0]=0ull; accA[c][1]=0ull; }
        {
            const float* hp = ht0s + (size_t)kA0*16 + bq*4;
            #pragma unroll 8
            for (int k=0;k<128;k++){
                float4 wv = *(const float4*)(wA + (size_t)k*4);
                ulonglong2 h2 = *(const ulonglong2*)(hp + (size_t)k*16);
                ull w0 = pack2(wv.x,wv.x), w1 = pack2(wv.y,wv.y);
                ull w2 = pack2(wv.z,wv.z), w3 = pack2(wv.w,wv.w);
                accA[0][0]=ffma2(w0,h2.x,accA[0][0]); accA[0][1]=ffma2(w0,h2.y,accA[0][1]);
                accA[1][0]=ffma2(w1,h2.x,accA[1][0]); accA[1][1]=ffma2(w1,h2.y,accA[1][1]);
                accA[2][0]=ffma2(w2,h2.x,accA[2][0]); accA[2][1]=ffma2(w2,h2.y,accA[2][1]);
                accA[3][0]=ffma2(w3,h2.x,accA[3][0]); accA[3][1]=ffma2(w3,h2.y,accA[3][1]);
            }
        }

        // ---- phase B: U1 (gmem stream), h1 (smem) ----
        ull accB[4][2];
        #pragma unroll
        for (int c=0;c<4;c++){ accB[c][0]=0ull; accB[c][1]=0ull; }
        #pragma unroll
        for (int i=0;i<8;i++)
            wb1[i] = __ldcg((const float4*)(UgB + (size_t)(kbB+8+i)*G4));
        {
            const float* hp = ht1s + bq*4;
            #pragma unroll
            for (int g=0; g<8; g++){
                #pragma unroll
                for (int i=0;i<8;i++){
                    int k = kbB + g*8 + i;
                    float4 wv = (g&1) ? wb1[i] : wb0[i];
                    ulonglong2 h2 = *(const ulonglong2*)(hp + (size_t)k*16);
                    ull w0 = pack2(wv.x,wv.x), w1 = pack2(wv.y,wv.y);
                    ull w2 = pack2(wv.z,wv.z), w3 = pack2(wv.w,wv.w);
                    accB[0][0]=ffma2(w0,h2.x,accB[0][0]); accB[0][1]=ffma2(w0,h2.y,accB[0][1]);
                    accB[1][0]=ffma2(w1,h2.x,accB[1][0]); accB[1][1]=ffma2(w1,h2.y,accB[1][1]);
                    accB[2][0]=ffma2(w2,h2.x,accB[2][0]); accB[2][1]=ffma2(w2,h2.y,accB[2][1]);
                    accB[3][0]=ffma2(w3,h2.x,accB[3][0]); accB[3][1]=ffma2(w3,h2.y,accB[3][1]);
                    if (g < 6){
                        if (g&1) wb1[i] = __ldcg((const float4*)(UgB + (size_t)(k+16)*G4));
                        else     wb0[i] = __ldcg((const float4*)(UgB + (size_t)(k+16)*G4));
                    }
                }
            }
        }

        // ---- write partials ----
        #pragma unroll
        for (int c=0;c<4;c++){
            int col = cq*4 + c;
            #pragma unroll
            for (int p=0;p<2;p++){
                int bp = bq*2 + p;
                zpAu[((size_t)wid*32 + col)*8 + bp] = accA[c][p];
                zpBu[((size_t)wid*32 + col)*8 + bp] = accB[c][p];
            }
        }
        __syncthreads();

        // ---- activation / state update ----
        {
            int layer = tid >> 7, id = tid & 127;
            int uu = id >> 4, b = id & 15;
            int bp = b >> 1, par = b & 1;
            if (layer == 0){
                if (s < NS){
                    int t = s;
                    float z[4];
                    #pragma unroll
                    for (int g=0; g<4; g++){
                        int col = g*8 + uu;
                        float a = Xp[(size_t)((t<<4)+b)*G4 + g*512 + u0 + uu];
                        #pragma unroll
                        for (int w=0; w<4; w++)
                            a += zpAf[(((size_t)w*32 + col)*8 + bp)*2 + par];
                        z[g] = a;
                    }
                    float cold = c0s[id];
                    float cn = sigf(z[1])*cold + sigf(z[0])*tanhfast(z[2]);
                    float hn = sigf(z[3])*tanhfast(cn);
                    int pos = dir ? (127 - t) : t;
                    if (seqs[b*TT + pos] == 0){
                        cn = cold; hn = ht0s[(u0+uu)*16 + b];
                    }
                    c0s[id] = cn;
                    g_h0t[dir][s&1][(u0+uu)*16 + b] = hn;
                }
            } else {
                if (s >= 1){
                    int t = s - 1;
                    float z[4];
                    #pragma unroll
                    for (int g=0; g<4; g++){
                        int col = g*8 + uu;
                        float a = b1[g*512 + u0 + uu];
                        #pragma unroll
                        for (int w=4; w<8; w++)
                            a += zpAf[(((size_t)w*32 + col)*8 + bp)*2 + par];
                        #pragma unroll
                        for (int w=0; w<8; w++)
                            a += zpBf[(((size_t)w*32 + col)*8 + bp)*2 + par];
                        z[g] = a;
                    }
                    float cold = c1s[id];
                    float cn = sigf(z[1])*cold + sigf(z[0])*tanhfast(z[2]);
                    float hn = sigf(z[3])*tanhfast(cn);
                    int pos = dir ? (127 - t) : t;
                    if (seqs[b*TT + pos] == 0){
                        cn = cold; hn = ht1s[(u0+uu)*16 + b];
                    }
                    c1s[id] = cn;
                    g_h1t[dir][(s+1)&1][(u0+uu)*16 + b] = hn;
                    // direct fp16 write into the projection A operand
                    int r = dir ? (b*NS + (125 - t)) : (b*NS + t);
                    A_h[(size_t)r*OC + dir*UH + u0 + uu] = __float2half_rn(hn);
                }
            }
        }

        // ---- grid barrier ----
        __threadfence();
        __syncthreads();
        if (tid == 0){
            unsigned v = atomicAdd(&g_cnt, 1u) + 1u;
            unsigned tgt = (unsigned)NBLK * (unsigned)(s+1);
            if (v == tgt) g_gen = (unsigned)(s+1);
            else while (g_gen < (unsigned)(s+1)) { }
        }
        __syncthreads();
    }
}

// ---------------- fp16 pack kernel for B ----------------
__global__ __launch_bounds__(256) void k_splitB(const float* __restrict__ Wp){
    __shared__ float tile[32][33];
    int n0 = blockIdx.x*32, k0 = blockIdx.y*32;
    int tx = threadIdx.x & 31, ty = threadIdx.x >> 5;
    #pragma unroll
    for (int i=0;i<4;i++){
        int k = k0 + ty + i*8;
        tile[ty+i*8][tx] = Wp[(size_t)k*V + n0 + tx];
    }
    __syncthreads();
    #pragma unroll
    for (int i=0;i<4;i++){
        int n = n0 + ty + i*8;
        float x = tile[tx][ty+i*8];
        B_h[(size_t)n*1024 + k0 + tx] = __float2half_rn(x);
    }
}

// ---------------- HMMA projection: single K=1024 GEMM ----------------
#define PBM 256
#define PBN 128
#define PADK 40
#define PA_FL (2*PBM*PADK)
#define PB_FL (2*PBN*PADK)
#define PJ_SMEM ((PA_FL + PB_FL)*2)

__global__ __launch_bounds__(512,1) void k_projhm(const float* __restrict__ bp,
                                                  float* __restrict__ Cout){
    extern __shared__ __half hsm[];
    __half* Asm = hsm;
    __half* Bsm = hsm + PA_FL;

    const int tid  = threadIdx.x;
    const int wid  = tid >> 5;
    const int lane = tid & 31;
    const int m0 = blockIdx.y * PBM, n0 = blockIdx.x * PBN;
    const int wm = (wid & 3) * 64;
    const int wn = (wid >> 2) * 32;

    float acc[4][4][4];
    #pragma unroll
    for (int mf=0; mf<4; mf++)
        #pragma unroll
        for (int nf=0; nf<4; nf++)
            #pragma unroll
            for (int i=0; i<4; i++) acc[mf][nf][i] = 0.f;

    const int arow = tid >> 2, asg = tid & 3;
    const int brow = tid >> 2, bsg = tid & 3;
    uint32_t aDst0 = smem_u32(Asm);
    uint32_t bDst0 = smem_u32(Bsm);

    #define LOAD_CHUNK(buf, kc) do { \
        uint32_t ab = aDst0 + (buf)*PBM*PADK*2; \
        cpa16(ab + (arow*PADK + asg*8)*2, \
              &A_h[(size_t)(m0 + arow)*1024 + (kc) + asg*8]); \
        cpa16(ab + ((arow+128)*PADK + asg*8)*2, \
              &A_h[(size_t)(m0 + arow + 128)*1024 + (kc) + asg*8]); \
        uint32_t bb2 = bDst0 + (buf)*PBN*PADK*2; \
        cpa16(bb2 + (brow*PADK + bsg*8)*2, \
              &B_h[(size_t)(n0 + brow)*1024 + (kc) + bsg*8]); \
        CPA_COMMIT(); \
    } while(0)

    LOAD_CHUNK(0, 0);

    for (int kk = 0; kk < 32; kk++){
        int buf = kk & 1;
        if (kk < 31){
            LOAD_CHUNK(buf^1, (kk+1)*32);
            CPA_WAIT1();
        } else {
            CPA_WAIT0();
        }
        __syncthreads();

        const uint32_t aBase = aDst0 + buf*PBM*PADK*2;
        const uint32_t bBase = bDst0 + buf*PBN*PADK*2;
        #pragma unroll
        for (int kf = 0; kf < 2; kf++){
            uint32_t a[4][4], b[4][2];
            int acol = kf*16 + ((lane & 16) ? 8 : 0);
            #pragma unroll
            for (int mf = 0; mf < 4; mf++){
                uint32_t addr = aBase + ((wm + mf*16 + (lane & 15))*PADK + acol)*2;
                LDSM_X4(a[mf][0], a[mf][1], a[mf][2], a[mf][3], addr);
            }
            int bcol = kf*16 + ((lane & 8) ? 8 : 0);
            #pragma unroll
            for (int nf = 0; nf < 4; nf++){
                uint32_t addr = bBase + ((wn + nf*8 + (lane & 7))*PADK + bcol)*2;
                LDSM_X2(b[nf][0], b[nf][1], addr);
            }
            #pragma unroll
            for (int mf = 0; mf < 4; mf++)
                #pragma unroll
                for (int nf = 0; nf < 4; nf++)
                    MMA16816(acc[mf][nf], a[mf], b[nf]);
        }
        __syncthreads();
    }

    const int g = lane >> 2, tg = lane & 3;
    #pragma unroll
    for (int nf = 0; nf < 4; nf++){
        int n = n0 + wn + nf*8 + tg*2;
        float b0 = bp[n], b1 = bp[n+1];
        #pragma unroll
        for (int mf = 0; mf < 4; mf++){
            int m = m0 + wm + mf*16 + g;
            if (m < OROWS){
                float2 st; st.x = acc[mf][nf][0] + b0; st.y = acc[mf][nf][1] + b1;
                *(float2*)&Cout[(size_t)m*V + n] = st;
            }
            if (m + 8 < OROWS){
                float2 st; st.x = acc[mf][nf][2] + b0; st.y = acc[mf][nf][3] + b1;
                *(float2*)&Cout[(size_t)(m+8)*V + n] = st;
            }
        }
    }
}

// ---------------- launch ----------------
extern "C" void kernel_launch(void* const* d_in, const int* in_sizes, int n_in,
                              void* d_out, int out_size)
{
    const int*   seqs  = (const int*)  d_in[0];
    const float* embed = (const float*)d_in[1];
    const float* fW0   = (const float*)d_in[2];
    const float* fU0   = (const float*)d_in[3];
    const float* fb0   = (const float*)d_in[4];
    const float* fW1   = (const float*)d_in[5];
    const float* fU1   = (const float*)d_in[6];
    const float* fb1   = (const float*)d_in[7];
    const float* bW0   = (const float*)d_in[8];
    const float* bU0   = (const float*)d_in[9];
    const float* bb0   = (const float*)d_in[10];
    const float* bW1   = (const float*)d_in[11];
    const float* bU1   = (const float*)d_in[12];
    const float* bb1   = (const float*)d_in[13];
    const float* Wp    = (const float*)d_in[14];
    const float* bp    = (const float*)d_in[15];
    float* out = (float*)d_out;

    const int RSMEM = RSMEM_FL * 4;
    cudaFuncSetAttribute(k_recur, cudaFuncAttributeMaxDynamicSharedMemorySize, RSMEM);
    cudaFuncSetAttribute(k_projhm, cudaFuncAttributeMaxDynamicSharedMemorySize, PJ_SMEM);

    k_init<<<(2*2*UH*BB + 255)/256, 256>>>();
    k_embed<<<(BB*TT*(D/4) + 255)/256, 256>>>(seqs, embed);

    dim3 gx(8, 16, 2);
    k_xprep<<<gx, 256>>>(fW0, fb0, bW0, bb0);

    dim3 gb(V/32, OC/32, 1);
    k_splitB<<<gb, 256>>>(Wp);

    k_recur<<<NBLK, 256, RSMEM>>>(fU0, fW1, fU1, fb1, bU0, bW1, bU1, bb1, seqs);

    dim3 gp(V/PBN, 2048/PBM, 1);
    k_projhm<<<gp, 512, PJ_SMEM>>>(bp, out);
}

// round 10
// speedup vs baseline: 5.5507x; 1.0496x over previous
#include <cuda_runtime.h>
#include <cuda_fp16.h>
#include <cstdint>
#include <math.h>

#define V   32000
#define D   256
#define UH  512
#define BB  16
#define TT  128
#define NS  126
#define G4  2048
#define OROWS (BB*NS)
#define OC  1024
#define NBLK 128
#define NSTEP 127

typedef unsigned long long ull;

// ---------------- device scratch ----------------
__device__ float g_emb[BB*TT*D];
__device__ float g_X[2][NS*BB*G4];
__device__ float g_h0t[2][2][UH*BB];
__device__ float g_h1t[2][2][UH*BB];
__device__ unsigned g_cnt2[2*32];             // per-direction barrier counters (padded)
__device__ volatile unsigned g_gen2[2*32];
// fp16 operands for HMMA projection (A_h rows >= OROWS stay zero-initialized)
__device__ __half A_h[(size_t)2048*1024];     // [m][k]  (concat h, fp16)
__device__ __half B_h[(size_t)32000*1024];    // [n][k]  (Wp^T, fp16)

// ---------------- f32x2 helpers ----------------
__device__ __forceinline__ ull pack2(float lo, float hi){
    ull r;
    asm("mov.b64 %0, {%1,%2};" : "=l"(r)
        : "r"(__float_as_uint(lo)), "r"(__float_as_uint(hi)));
    return r;
}
__device__ __forceinline__ void unpack2(ull v, float& lo, float& hi){
    unsigned a, b;
    asm("mov.b64 {%0,%1}, %2;" : "=r"(a), "=r"(b) : "l"(v));
    lo = __uint_as_float(a); hi = __uint_as_float(b);
}
__device__ __forceinline__ ull ffma2(ull a, ull b, ull c){
    ull r;
    asm("fma.rn.f32x2 %0, %1, %2, %3;" : "=l"(r) : "l"(a), "l"(b), "l"(c));
    return r;
}
__device__ __forceinline__ float sigf(float x){ return 1.f/(1.f + __expf(-x)); }
__device__ __forceinline__ float tanhfast(float x){ return 2.f/(1.f + __expf(-2.f*x)) - 1.f; }

// ---------------- arch-neutral PTX helpers ----------------
__device__ __forceinline__ uint32_t smem_u32(const void* p){
    uint32_t a;
    asm("{ .reg .u64 t; cvta.to.shared.u64 t, %1; cvt.u32.u64 %0, t; }" : "=r"(a) : "l"(p));
    return a;
}
__device__ __forceinline__ void cpa16(uint32_t s, const void* g){
    asm volatile("cp.async.cg.shared.global [%0], [%1], 16;" :: "r"(s), "l"(g) : "memory");
}
#define CPA_COMMIT() asm volatile("cp.async.commit_group;" ::: "memory")
#define CPA_WAIT1()  asm volatile("cp.async.wait_group 1;" ::: "memory")
#define CPA_WAIT0()  asm volatile("cp.async.wait_group 0;" ::: "memory")

#define LDSM_X4(r0,r1,r2,r3,addr) \
    asm volatile("ldmatrix.sync.aligned.m8n8.x4.shared.b16 {%0,%1,%2,%3}, [%4];" \
        : "=r"(r0), "=r"(r1), "=r"(r2), "=r"(r3) : "r"(addr))
#define LDSM_X2(r0,r1,addr) \
    asm volatile("ldmatrix.sync.aligned.m8n8.x2.shared.b16 {%0,%1}, [%2];" \
        : "=r"(r0), "=r"(r1) : "r"(addr))
#define MMA16816(c,a,b) \
    asm volatile("mma.sync.aligned.m16n8k16.row.col.f32.f16.f16.f32 " \
        "{%0,%1,%2,%3}, {%4,%5,%6,%7}, {%8,%9}, {%0,%1,%2,%3};" \
        : "+f"((c)[0]), "+f"((c)[1]), "+f"((c)[2]), "+f"((c)[3]) \
        : "r"((a)[0]), "r"((a)[1]), "r"((a)[2]), "r"((a)[3]), \
          "r"((b)[0]), "r"((b)[1]))

// ---------------- init (every replay) ----------------
__global__ void k_init(){
    int i = blockIdx.x*blockDim.x + threadIdx.x;
    int n = 2*2*UH*BB;
    if (i < n){
        ((float*)g_h0t)[i] = 0.f;
        ((float*)g_h1t)[i] = 0.f;
    }
    if (i < 64){ g_cnt2[i] = 0u; g_gen2[i] = 0u; }
}

// ---------------- embedding gather ----------------
__global__ void k_embed(const int* __restrict__ seqs, const float* __restrict__ embed){
    int i = blockIdx.x*blockDim.x + threadIdx.x;
    if (i >= BB*TT*(D/4)) return;
    int bt = i / (D/4);
    int d4 = i % (D/4);
    int tok = seqs[bt];
    float4 v = *(const float4*)&embed[(size_t)tok*D + d4*4];
    *(float4*)&g_emb[(size_t)bt*D + d4*4] = v;
}

// ---------------- X precompute GEMM (fp32 FFMA2) ----------------
__global__ __launch_bounds__(256) void k_xprep(const float* __restrict__ fW0,
                                               const float* __restrict__ fb0,
                                               const float* __restrict__ bW0,
                                               const float* __restrict__ bb0){
    const int dir = blockIdx.z;
    const float* W    = dir ? bW0 : fW0;
    const float* bias = dir ? bb0 : fb0;
    float* out = g_X[dir];
    const int m0 = blockIdx.y*128, n0 = blockIdx.x*256;
    __shared__ float As[16][128];
    __shared__ float Bs[16][256];
    const int tid = threadIdx.x;
    const int tx = tid & 15, ty = tid >> 4;

    ull acc[8][8];
    #pragma unroll
    for (int i=0;i<8;i++)
        #pragma unroll
        for (int q=0;q<8;q++) acc[i][q] = 0ull;

    for (int kt=0; kt<16; kt++){
        #pragma unroll
        for (int i=0;i<2;i++){
            int lin = tid + i*256;
            int row = lin>>2, c4 = lin&3;
            int r = m0 + row;
            float4 v = make_float4(0.f,0.f,0.f,0.f);
            if (r < OROWS){
                int t = r>>4, b = r&15;
                int txi = dir ? (127 - t) : t;
                v = *(const float4*)&g_emb[((b<<7)+txi)*D + kt*16 + c4*4];
            }
            As[c4*4+0][row]=v.x; As[c4*4+1][row]=v.y;
            As[c4*4+2][row]=v.z; As[c4*4+3][row]=v.w;
        }
        #pragma unroll
        for (int i=0;i<4;i++){
            int lin = tid + i*256;
            int kr = lin>>6, c4 = lin&63;
            *(float4*)&Bs[kr][c4*4] =
                *(const float4*)&W[(size_t)(kt*16+kr)*G4 + n0 + c4*4];
        }
        __syncthreads();
        #pragma unroll
        for (int k=0;k<16;k++){
            float a0[8];
            *(float4*)&a0[0] = *(float4*)&As[k][ty*8];
            *(float4*)&a0[4] = *(float4*)&As[k][ty*8+4];
            ull av[8];
            #pragma unroll
            for (int i=0;i<8;i++) av[i] = pack2(a0[i], a0[i]);
            ull bv[8];
            #pragma unroll
            for (int q=0;q<4;q++){
                ulonglong2 p = *(const ulonglong2*)&Bs[k][tx*16 + q*4];
                bv[2*q] = p.x; bv[2*q+1] = p.y;
            }
            #pragma unroll
            for (int i=0;i<8;i++)
                #pragma unroll
                for (int q=0;q<8;q++)
                    acc[i][q] = ffma2(av[i], bv[q], acc[i][q]);
        }
        __syncthreads();
    }
    #pragma unroll
    for (int i=0;i<8;i++){
        int r = m0 + ty*8 + i;
        if (r >= OROWS) continue;
        float* crow = out + (size_t)r*G4 + n0 + tx*16;
        #pragma unroll
        for (int q=0;q<8;q++){
            float lo,hi; unpack2(acc[i][q], lo, hi);
            int col = n0 + tx*16 + 2*q;
            float2 st; st.x = lo + bias[col]; st.y = hi + bias[col+1];
            *(float2*)&crow[2*q] = st;
        }
    }
}

// ---------------- persistent recurrence ----------------
#define WSQ_FL   (8*1025*4)
#define HT_FL    (UH*BB)
#define ZP_FL    (8*32*8*2)
#define RSMEM_FL (WSQ_FL + 2*HT_FL + 2*ZP_FL + 256)

__global__ __launch_bounds__(256,1) void k_recur(
    const float* __restrict__ fU0, const float* __restrict__ fW1,
    const float* __restrict__ fU1, const float* __restrict__ fb1,
    const float* __restrict__ bU0, const float* __restrict__ bW1,
    const float* __restrict__ bU1, const float* __restrict__ bb1,
    const int*   __restrict__ seqs)
{
    extern __shared__ float sm[];
    float* wsQ  = sm;                          // [cq][k] float4 stride 1025
    float* ht0s = sm + WSQ_FL;                 // [k][16]
    float* ht1s = ht0s + HT_FL;
    float* zpAf = ht1s + HT_FL;                // [w][32][8][2]
    float* zpBf = zpAf + ZP_FL;
    float* c0s  = zpBf + ZP_FL;                // [128]
    float* c1s  = c0s + 128;
    ull* zpAu = (ull*)zpAf;
    ull* zpBu = (ull*)zpBf;

    const int tid  = threadIdx.x;
    const int wid  = tid >> 5;
    const int lane = tid & 31;
    const int blk  = blockIdx.x;
    const int dir  = blk >> 6;
    const int u0   = (blk & 63) * 8;

    const float* U0 = dir ? bU0 : fU0;
    const float* W1 = dir ? bW1 : fW1;
    const float* U1 = dir ? bU1 : fU1;
    const float* b1 = dir ? bb1 : fb1;
    const float* Xp = g_X[dir];

    // ---- preload U0|W1 into wsQuad (once) ----
    for (int idx = tid; idx < 8*1024; idx += 256){
        int cq = idx >> 10, k = idx & 1023;
        int kk = k & 511;
        const float* Wsrc = (k < 512) ? U0 : W1;
        int jb = (cq>>1)*512 + u0 + (cq&1)*4;
        float4 v = *(const float4*)&Wsrc[(size_t)kk*G4 + jb];
        *(float4*)&wsQ[((size_t)cq*1025 + k)*4] = v;
    }
    if (tid < 128){ c0s[tid] = 0.f; c1s[tid] = 0.f; }
    __syncthreads();

    const int cq = lane & 7;          // col quad: cols 4cq..4cq+3
    const int bq = lane >> 3;         // batch quad: batches 4bq..4bq+3
    const int kbA = wid * 128;        // phase A weight k-range (0..1023)
    const int kA0 = kbA & 511;        // phase A h-index base (both halves read ht0s)
    const int kbB = wid * 64;         // phase B k-range (0..511)
    const float* wA = wsQ + ((size_t)cq*1025 + kbA)*4;
    const float* UgB = U1 + (size_t)((cq>>1)*512 + u0 + (cq&1)*4);
    const uint32_t d0s = smem_u32(ht0s);
    const uint32_t d1s = smem_u32(ht1s);
    unsigned* cnt = &g_cnt2[dir*32];
    volatile unsigned* gen = &g_gen2[dir*32];

    for (int s = 0; s < NSTEP; s++){
        // ---- async-stage h0[s-1] (group A) and h1[s-2] (group B) ----
        {
            const float4* s0 = (const float4*)g_h0t[dir][(s+1)&1];
            const float4* s1 = (const float4*)g_h1t[dir][s&1];
            #pragma unroll
            for (int i=0;i<8;i++){ int ix = tid + i*256; cpa16(d0s + ix*16, s0+ix); }
            CPA_COMMIT();
            #pragma unroll
            for (int i=0;i<8;i++){ int ix = tid + i*256; cpa16(d1s + ix*16, s1+ix); }
            CPA_COMMIT();
        }

        // phase-B U1 group-0 prefetch — latency hides under staging + phase A
        float4 wb0[8], wb1[8];
        #pragma unroll
        for (int i=0;i<8;i++)
            wb0[i] = __ldcg((const float4*)(UgB + (size_t)(kbB+i)*G4));

        CPA_WAIT1();            // ht0 resident (ht1 may still be in flight)
        __syncthreads();

        // ---- phase A: U0|W1 (smem weights), h0 (smem) ----
        ull accA[4][2];
        #pragma unroll
        for (int c=0;c<4;c++){ accA[c][0]=0ull; accA[c][1]=0ull; }
        {
            const float* hp = ht0s + (size_t)kA0*16 + bq*4;
            #pragma unroll 8
            for (int k=0;k<128;k++){
                float4 wv = *(const float4*)(wA + (size_t)k*4);
                ulonglong2 h2 = *(const ulonglong2*)(hp + (size_t)k*16);
                ull w0 = pack2(wv.x,wv.x), w1 = pack2(wv.y,wv.y);
                ull w2 = pack2(wv.z,wv.z), w3 = pack2(wv.w,wv.w);
                accA[0][0]=ffma2(w0,h2.x,accA[0][0]); accA[0][1]=ffma2(w0,h2.y,accA[0][1]);
                accA[1][0]=ffma2(w1,h2.x,accA[1][0]); accA[1][1]=ffma2(w1,h2.y,accA[1][1]);
                accA[2][0]=ffma2(w2,h2.x,accA[2][0]); accA[2][1]=ffma2(w2,h2.y,accA[2][1]);
                accA[3][0]=ffma2(w3,h2.x,accA[3][0]); accA[3][1]=ffma2(w3,h2.y,accA[3][1]);
            }
        }

        CPA_WAIT0();            // ht1 resident
        __syncthreads();

        // ---- phase B: U1 (gmem stream), h1 (smem) ----
        ull accB[4][2];
        #pragma unroll
        for (int c=0;c<4;c++){ accB[c][0]=0ull; accB[c][1]=0ull; }
        #pragma unroll
        for (int i=0;i<8;i++)
            wb1[i] = __ldcg((const float4*)(UgB + (size_t)(kbB+8+i)*G4));
        {
            const float* hp = ht1s + bq*4;
            #pragma unroll
            for (int g=0; g<8; g++){
                #pragma unroll
                for (int i=0;i<8;i++){
                    int k = kbB + g*8 + i;
                    float4 wv = (g&1) ? wb1[i] : wb0[i];
                    ulonglong2 h2 = *(const ulonglong2*)(hp + (size_t)k*16);
                    ull w0 = pack2(wv.x,wv.x), w1 = pack2(wv.y,wv.y);
                    ull w2 = pack2(wv.z,wv.z), w3 = pack2(wv.w,wv.w);
                    accB[0][0]=ffma2(w0,h2.x,accB[0][0]); accB[0][1]=ffma2(w0,h2.y,accB[0][1]);
                    accB[1][0]=ffma2(w1,h2.x,accB[1][0]); accB[1][1]=ffma2(w1,h2.y,accB[1][1]);
                    accB[2][0]=ffma2(w2,h2.x,accB[2][0]); accB[2][1]=ffma2(w2,h2.y,accB[2][1]);
                    accB[3][0]=ffma2(w3,h2.x,accB[3][0]); accB[3][1]=ffma2(w3,h2.y,accB[3][1]);
                    if (g < 6){
                        if (g&1) wb1[i] = __ldcg((const float4*)(UgB + (size_t)(k+16)*G4));
                        else     wb0[i] = __ldcg((const float4*)(UgB + (size_t)(k+16)*G4));
                    }
                }
            }
        }

        // ---- write partials ----
        #pragma unroll
        for (int c=0;c<4;c++){
            int col = cq*4 + c;
            #pragma unroll
            for (int p=0;p<2;p++){
                int bp = bq*2 + p;
                zpAu[((size_t)wid*32 + col)*8 + bp] = accA[c][p];
                zpBu[((size_t)wid*32 + col)*8 + bp] = accB[c][p];
            }
        }
        __syncthreads();

        // ---- activation / state update ----
        {
            int layer = tid >> 7, id = tid & 127;
            int uu = id >> 4, b = id & 15;
            int bp = b >> 1, par = b & 1;
            if (layer == 0){
                if (s < NS){
                    int t = s;
                    float z[4];
                    #pragma unroll
                    for (int g=0; g<4; g++){
                        int col = g*8 + uu;
                        float a = Xp[(size_t)((t<<4)+b)*G4 + g*512 + u0 + uu];
                        #pragma unroll
                        for (int w=0; w<4; w++)
                            a += zpAf[(((size_t)w*32 + col)*8 + bp)*2 + par];
                        z[g] = a;
                    }
                    float cold = c0s[id];
                    float cn = sigf(z[1])*cold + sigf(z[0])*tanhfast(z[2]);
                    float hn = sigf(z[3])*tanhfast(cn);
                    int pos = dir ? (127 - t) : t;
                    if (seqs[b*TT + pos] == 0){
                        cn = cold; hn = ht0s[(u0+uu)*16 + b];
                    }
                    c0s[id] = cn;
                    g_h0t[dir][s&1][(u0+uu)*16 + b] = hn;
                }
            } else {
                if (s >= 1){
                    int t = s - 1;
                    float z[4];
                    #pragma unroll
                    for (int g=0; g<4; g++){
                        int col = g*8 + uu;
                        float a = b1[g*512 + u0 + uu];
                        #pragma unroll
                        for (int w=4; w<8; w++)
                            a += zpAf[(((size_t)w*32 + col)*8 + bp)*2 + par];
                        #pragma unroll
                        for (int w=0; w<8; w++)
                            a += zpBf[(((size_t)w*32 + col)*8 + bp)*2 + par];
                        z[g] = a;
                    }
                    float cold = c1s[id];
                    float cn = sigf(z[1])*cold + sigf(z[0])*tanhfast(z[2]);
                    float hn = sigf(z[3])*tanhfast(cn);
                    int pos = dir ? (127 - t) : t;
                    if (seqs[b*TT + pos] == 0){
                        cn = cold; hn = ht1s[(u0+uu)*16 + b];
                    }
                    c1s[id] = cn;
                    g_h1t[dir][(s+1)&1][(u0+uu)*16 + b] = hn;
                    // direct fp16 write into the projection A operand
                    int r = dir ? (b*NS + (125 - t)) : (b*NS + t);
                    A_h[(size_t)r*OC + dir*UH + u0 + uu] = __float2half_rn(hn);
                }
            }
        }

        // ---- per-direction grid barrier (64 blocks) ----
        __syncthreads();
        if (tid == 0){
            __threadfence();
            unsigned v = atomicAdd(cnt, 1u) + 1u;
            unsigned tgt = 64u * (unsigned)(s+1);
            if (v == tgt) *gen = (unsigned)(s+1);
            else while (*gen < (unsigned)(s+1)) __nanosleep(64);
        }
        __syncthreads();
    }
}

// ---------------- fp16 pack kernel for B ----------------
__global__ __launch_bounds__(256) void k_splitB(const float* __restrict__ Wp){
    __shared__ float tile[32][33];
    int n0 = blockIdx.x*32, k0 = blockIdx.y*32;
    int tx = threadIdx.x & 31, ty = threadIdx.x >> 5;
    #pragma unroll
    for (int i=0;i<4;i++){
        int k = k0 + ty + i*8;
        tile[ty+i*8][tx] = Wp[(size_t)k*V + n0 + tx];
    }
    __syncthreads();
    #pragma unroll
    for (int i=0;i<4;i++){
        int n = n0 + ty + i*8;
        float x = tile[tx][ty+i*8];
        B_h[(size_t)n*1024 + k0 + tx] = __float2half_rn(x);
    }
}

// ---------------- HMMA projection: single K=1024 GEMM ----------------
#define PBM 256
#define PBN 128
#define PADK 40
#define PA_FL (2*PBM*PADK)
#define PB_FL (2*PBN*PADK)
#define PJ_SMEM ((PA_FL + PB_FL)*2)

__global__ __launch_bounds__(512,1) void k_projhm(const float* __restrict__ bp,
                                                  float* __restrict__ Cout){
    extern __shared__ __half hsm[];
    __half* Asm = hsm;
    __half* Bsm = hsm + PA_FL;

    const int tid  = threadIdx.x;
    const int wid  = tid >> 5;
    const int lane = tid & 31;
    const int m0 = blockIdx.y * PBM, n0 = blockIdx.x * PBN;
    const int wm = (wid & 3) * 64;
    const int wn = (wid >> 2) * 32;

    float acc[4][4][4];
    #pragma unroll
    for (int mf=0; mf<4; mf++)
        #pragma unroll
        for (int nf=0; nf<4; nf++)
            #pragma unroll
            for (int i=0; i<4; i++) acc[mf][nf][i] = 0.f;

    const int arow = tid >> 2, asg = tid & 3;
    const int brow = tid >> 2, bsg = tid & 3;
    uint32_t aDst0 = smem_u32(Asm);
    uint32_t bDst0 = smem_u32(Bsm);

    #define LOAD_CHUNK(buf, kc) do { \
        uint32_t ab = aDst0 + (buf)*PBM*PADK*2; \
        cpa16(ab + (arow*PADK + asg*8)*2, \
              &A_h[(size_t)(m0 + arow)*1024 + (kc) + asg*8]); \
        cpa16(ab + ((arow+128)*PADK + asg*8)*2, \
              &A_h[(size_t)(m0 + arow + 128)*1024 + (kc) + asg*8]); \
        uint32_t bb2 = bDst0 + (buf)*PBN*PADK*2; \
        cpa16(bb2 + (brow*PADK + bsg*8)*2, \
              &B_h[(size_t)(n0 + brow)*1024 + (kc) + bsg*8]); \
        CPA_COMMIT(); \
    } while(0)

    LOAD_CHUNK(0, 0);

    for (int kk = 0; kk < 32; kk++){
        int buf = kk & 1;
        if (kk < 31){
            LOAD_CHUNK(buf^1, (kk+1)*32);
            CPA_WAIT1();
        } else {
            CPA_WAIT0();
        }
        __syncthreads();

        const uint32_t aBase = aDst0 + buf*PBM*PADK*2;
        const uint32_t bBase = bDst0 + buf*PBN*PADK*2;
        #pragma unroll
        for (int kf = 0; kf < 2; kf++){
            uint32_t a[4][4], b[4][2];
            int acol = kf*16 + ((lane & 16) ? 8 : 0);
            #pragma unroll
            for (int mf = 0; mf < 4; mf++){
                uint32_t addr = aBase + ((wm + mf*16 + (lane & 15))*PADK + acol)*2;
                LDSM_X4(a[mf][0], a[mf][1], a[mf][2], a[mf][3], addr);
            }
            int bcol = kf*16 + ((lane & 8) ? 8 : 0);
            #pragma unroll
            for (int nf = 0; nf < 4; nf++){
                uint32_t addr = bBase + ((wn + nf*8 + (lane & 7))*PADK + bcol)*2;
                LDSM_X2(b[nf][0], b[nf][1], addr);
            }
            #pragma unroll
            for (int mf = 0; mf < 4; mf++)
                #pragma unroll
                for (int nf = 0; nf < 4; nf++)
                    MMA16816(acc[mf][nf], a[mf], b[nf]);
        }
        __syncthreads();
    }

    const int g = lane >> 2, tg = lane & 3;
    #pragma unroll
    for (int nf = 0; nf < 4; nf++){
        int n = n0 + wn + nf*8 + tg*2;
        float b0 = bp[n], b1 = bp[n+1];
        #pragma unroll
        for (int mf = 0; mf < 4; mf++){
            int m = m0 + wm + mf*16 + g;
            if (m < OROWS){
                float2 st; st.x = acc[mf][nf][0] + b0; st.y = acc[mf][nf][1] + b1;
                *(float2*)&Cout[(size_t)m*V + n] = st;
            }
            if (m + 8 < OROWS){
                float2 st; st.x = acc[mf][nf][2] + b0; st.y = acc[mf][nf][3] + b1;
                *(float2*)&Cout[(size_t)(m+8)*V + n] = st;
            }
        }
    }
}

// ---------------- launch ----------------
extern "C" void kernel_launch(void* const* d_in, const int* in_sizes, int n_in,
                              void* d_out, int out_size)
{
    const int*   seqs  = (const int*)  d_in[0];
    const float* embed = (const float*)d_in[1];
    const float* fW0   = (const float*)d_in[2];
    const float* fU0   = (const float*)d_in[3];
    const float* fb0   = (const float*)d_in[4];
    const float* fW1   = (const float*)d_in[5];
    const float* fU1   = (const float*)d_in[6];
    const float* fb1   = (const float*)d_in[7];
    const float* bW0   = (const float*)d_in[8];
    const float* bU0   = (const float*)d_in[9];
    const float* bb0   = (const float*)d_in[10];
    const float* bW1   = (const float*)d_in[11];
    const float* bU1   = (const float*)d_in[12];
    const float* bb1   = (const float*)d_in[13];
    const float* Wp    = (const float*)d_in[14];
    const float* bp    = (const float*)d_in[15];
    float* out = (float*)d_out;

    const int RSMEM = RSMEM_FL * 4;
    cudaFuncSetAttribute(k_recur, cudaFuncAttributeMaxDynamicSharedMemorySize, RSMEM);
    cudaFuncSetAttribute(k_projhm, cudaFuncAttributeMaxDynamicSharedMemorySize, PJ_SMEM);

    k_init<<<(2*2*UH*BB + 255)/256, 256>>>();
    k_embed<<<(BB*TT*(D/4) + 255)/256, 256>>>(seqs, embed);

    dim3 gx(8, 16, 2);
    k_xprep<<<gx, 256>>>(fW0, fb0, bW0, bb0);

    dim3 gb(V/32, OC/32, 1);
    k_splitB<<<gb, 256>>>(Wp);

    k_recur<<<NBLK, 256, RSMEM>>>(fU0, fW1, fU1, fb1, bU0, bW1, bU1, bb1, seqs);

    dim3 gp(V/PBN, 2048/PBM, 1);
    k_projhm<<<gp, 512, PJ_SMEM>>>(bp, out);
}